// round 1
// baseline (speedup 1.0000x reference)
#include <cuda_runtime.h>
#include <math.h>
#include <stdint.h>

#define N_NODES 50000
#define N_EDGES 250000
#define DIM     256
#define NRELS   400
#define NSPEC   129      // rfft bins 0..128
#define SPEC_PAD 260     // 258 + 2 pad (keeps float4 alignment in GEMM)
#define AGGW    520      // 256 time + 258 spectral + 6 pad (K mult of 8, 16B rows)
#define LN_EPS  1e-5f

// ------------------------- scratch (device globals; no mallocs) -------------
__device__ float g_h  [(size_t)N_NODES * DIM];       // current node features
__device__ float g_HS [(size_t)N_NODES * SPEC_PAD];  // rfft(h)
__device__ float g_RS [(size_t)NRELS   * SPEC_PAD];  // rfft(rel)
__device__ float g_AGG[(size_t)N_NODES * AGGW];      // [aggT(256) | aggF(258) | pad]
__device__ float g_OUT[(size_t)N_NODES * DIM];
__device__ float g_Bf [DIM * SPEC_PAD];              // forward DFT basis [256][260]
__device__ float g_J  [258 * DIM];                   // inverse basis [258][256]
__device__ float g_Mw [AGGW * DIM];                  // [Wn^T ; J@Wn^T ; 0]
__device__ float g_w  [6];                           // softmax(cw1), softmax(cw2)

// ------------------------- table builders -----------------------------------
__global__ void build_bf_kernel(float* __restrict__ Bf) {
    int idx = blockIdx.x * blockDim.x + threadIdx.x;
    if (idx >= DIM * SPEC_PAD) return;
    int j = idx / SPEC_PAD, c = idx % SPEC_PAD;
    float v = 0.f;
    if (c < 258) {
        int k = c >> 1;
        double ang = (2.0 * (double)j * (double)k) / 256.0;  // in units of pi
        v = (c & 1) ? (float)(-sinpi(ang)) : (float)cospi(ang);
    }
    Bf[idx] = v;
}

__global__ void build_j_kernel(float* __restrict__ J) {
    int idx = blockIdx.x * blockDim.x + threadIdx.x;
    if (idx >= 258 * DIM) return;
    int rc = idx / DIM, n = idx % DIM;
    int k = rc >> 1;
    double s = ((k == 0) || (k == 128)) ? (1.0 / 256.0) : (2.0 / 256.0);
    double ang = (2.0 * (double)k * (double)n) / 256.0;
    J[idx] = (rc & 1) ? (float)(-s * sinpi(ang)) : (float)(s * cospi(ang));
}

__global__ void softmax_kernel(const float* __restrict__ cw1,
                               const float* __restrict__ cw2,
                               float* __restrict__ w) {
    if (threadIdx.x == 0 && blockIdx.x == 0) {
        for (int L = 0; L < 2; L++) {
            const float* c = (L == 0) ? cw1 : cw2;
            float m = fmaxf(c[0], fmaxf(c[1], c[2]));
            float e0 = expf(c[0] - m), e1 = expf(c[1] - m), e2 = expf(c[2] - m);
            float s = e0 + e1 + e2;
            w[L * 3 + 0] = e0 / s; w[L * 3 + 1] = e1 / s; w[L * 3 + 2] = e2 / s;
        }
    }
}

// Mw rows 0..255 = Wn^T ; rows 514..519 = 0 (rows 256..513 filled by GEMM J@Wn^T)
__global__ void prep_mw_kernel(const float* __restrict__ Wn, float* __restrict__ Mw) {
    int idx = blockIdx.x * blockDim.x + threadIdx.x;
    if (idx >= AGGW * DIM) return;
    int r = idx / DIM, c = idx % DIM;
    if (r < DIM)        Mw[idx] = Wn[c * DIM + r];
    else if (r >= 514)  Mw[idx] = 0.f;
}

// ------------------------- gather h = emb[x] ---------------------------------
__global__ void gather_kernel(const int* __restrict__ x,
                              const float* __restrict__ emb,
                              float* __restrict__ h) {
    int i = blockIdx.x * blockDim.x + threadIdx.x;   // over 50000*64 float4
    if (i >= N_NODES * (DIM / 4)) return;
    int v = i >> 6, c = i & 63;
    reinterpret_cast<float4*>(h)[(size_t)v * 64 + c] =
        reinterpret_cast<const float4*>(emb)[(size_t)x[v] * 64 + c];
}

// ------------------------- self-loop init (writes AGG) -----------------------
__global__ void node_init_kernel(const float* __restrict__ h,
                                 const float* __restrict__ HS,
                                 const float* __restrict__ rel,
                                 const float* __restrict__ RS,
                                 const float* __restrict__ w, int wofs,
                                 float* __restrict__ AGG) {
    int v = (blockIdx.x * blockDim.x + threadIdx.x) >> 5;
    if (v >= N_NODES) return;
    int lane = threadIdx.x & 31;
    float w0 = w[wofs + 0], w1 = w[wofs + 1], w2 = w[wofs + 2];
    const float* hv = h + (size_t)v * DIM;
    float* aggT = AGG + (size_t)v * AGGW;
#pragma unroll
    for (int i = 0; i < 8; i++) {
        int d = lane + 32 * i;
        float hd = hv[d], rd = rel[d];              // rel row 0 (self-loop type 0)
        aggT[d] = w0 * hd * rd + w1 * (hd + rd);
    }
    const float* Hs = HS + (size_t)v * SPEC_PAD;
    float* aggF = aggT + DIM;
    for (int k = lane; k < NSPEC; k += 32) {
        float2 a = *reinterpret_cast<const float2*>(Hs + 2 * k);
        float2 b = *reinterpret_cast<const float2*>(RS + 2 * k);  // RS row 0
        aggF[2 * k]     = w2 * (a.x * b.x + a.y * b.y);
        aggF[2 * k + 1] = w2 * (a.y * b.x - a.x * b.y);
    }
    if (lane < AGGW - 514) aggT[514 + lane] = 0.f;   // zero K-pad
}

// ------------------------- edge scatter (atomics) ----------------------------
__global__ void edge_kernel(const int* __restrict__ src,
                            const int* __restrict__ dst,
                            const int* __restrict__ et,
                            const float* __restrict__ h,
                            const float* __restrict__ HS,
                            const float* __restrict__ rel,
                            const float* __restrict__ RS,
                            const float* __restrict__ w, int wofs,
                            float* __restrict__ AGG) {
    int e = (blockIdx.x * blockDim.x + threadIdx.x) >> 5;
    if (e >= N_EDGES) return;
    int lane = threadIdx.x & 31;
    int s = src[e], v = dst[e], t = et[e];
    float w0 = w[wofs + 0], w1 = w[wofs + 1], w2 = w[wofs + 2];
    const float* hs = h   + (size_t)s * DIM;
    const float* rt = rel + (size_t)t * DIM;
    float* aggT = AGG + (size_t)v * AGGW;
#pragma unroll
    for (int i = 0; i < 8; i++) {
        int d = lane + 32 * i;
        float hd = hs[d], rd = rt[d];
        atomicAdd(&aggT[d], w0 * hd * rd + w1 * (hd + rd));
    }
    const float* Hs = HS + (size_t)s * SPEC_PAD;
    const float* Rt = RS + (size_t)t * SPEC_PAD;
    float* aggF = aggT + DIM;
    for (int k = lane; k < NSPEC; k += 32) {
        float2 a = *reinterpret_cast<const float2*>(Hs + 2 * k);
        float2 b = *reinterpret_cast<const float2*>(Rt + 2 * k);
        atomicAdd(&aggF[2 * k],     w2 * (a.x * b.x + a.y * b.y));
        atomicAdd(&aggF[2 * k + 1], w2 * (a.y * b.x - a.x * b.y));
    }
}

// ------------------------- residual + LayerNorm + ReLU -----------------------
__global__ void epilogue_kernel(const float* __restrict__ OUT,
                                const float* __restrict__ h_in,
                                const float* __restrict__ bn,
                                const float* __restrict__ gamma,
                                const float* __restrict__ beta,
                                float* __restrict__ h_out) {
    int v = (blockIdx.x * blockDim.x + threadIdx.x) >> 5;
    if (v >= N_NODES) return;
    int lane = threadIdx.x & 31;
    const float* o  = OUT  + (size_t)v * DIM;
    const float* hi = h_in + (size_t)v * DIM;
    float z[8];
    float s = 0.f;
#pragma unroll
    for (int i = 0; i < 8; i++) {
        int d = lane + 32 * i;
        z[i] = o[d] + bn[d] + hi[d];
        s += z[i];
    }
#pragma unroll
    for (int off = 16; off; off >>= 1) s += __shfl_xor_sync(0xffffffffu, s, off);
    float mu = s * (1.f / DIM);
    float vv = 0.f;
#pragma unroll
    for (int i = 0; i < 8; i++) { float t = z[i] - mu; vv += t * t; }
#pragma unroll
    for (int off = 16; off; off >>= 1) vv += __shfl_xor_sync(0xffffffffu, vv, off);
    float rstd = rsqrtf(vv * (1.f / DIM) + LN_EPS);
    float* ho = h_out + (size_t)v * DIM;
#pragma unroll
    for (int i = 0; i < 8; i++) {
        int d = lane + 32 * i;
        float y = (z[i] - mu) * rstd * gamma[d] + beta[d];
        ho[d] = fmaxf(y, 0.f);
    }
}

// ------------------------- fp32 SGEMM: C = A @ (TB ? B^T : B) (+bias) -------
// A:[M,K] rm. TB=0: B:[K,N] rm. TB=1: B:[N,K] rm. C:[M,N] rm.
// Requires K%8==0, A rows & (TB?K:N) 16B-aligned strides (true for all uses).
#define BM 128
#define BN 128
#define BK 8

template<bool TB, bool BIAS>
__global__ __launch_bounds__(256)
void sgemm_kernel(const float* __restrict__ A, const float* __restrict__ B,
                  float* __restrict__ C, const float* __restrict__ bias,
                  int M, int N, int K) {
    __shared__ __align__(16) float As[BK][BM];
    __shared__ __align__(16) float Bs[BK][BN];
    int tid = threadIdx.x;
    int tx = tid & 15, ty = tid >> 4;
    int bm = blockIdx.y * BM, bn = blockIdx.x * BN;

    int ar = tid >> 1;            // A tile row 0..127
    int ac = (tid & 1) << 2;      // A tile k 0 or 4
    float acc[8][8];
#pragma unroll
    for (int i = 0; i < 8; i++)
#pragma unroll
        for (int j = 0; j < 8; j++) acc[i][j] = 0.f;

    for (int k0 = 0; k0 < K; k0 += BK) {
        // load A tile (transposed into As[k][m])
        float4 av = make_float4(0.f, 0.f, 0.f, 0.f);
        int arow = bm + ar;
        if (arow < M)
            av = *reinterpret_cast<const float4*>(A + (size_t)arow * K + k0 + ac);
        As[ac + 0][ar] = av.x; As[ac + 1][ar] = av.y;
        As[ac + 2][ar] = av.z; As[ac + 3][ar] = av.w;
        // load B tile into Bs[k][n]
        if (TB) {
            int nr = tid >> 1, kc = (tid & 1) << 2;
            float4 bv = make_float4(0.f, 0.f, 0.f, 0.f);
            int nrow = bn + nr;
            if (nrow < N)
                bv = *reinterpret_cast<const float4*>(B + (size_t)nrow * K + k0 + kc);
            Bs[kc + 0][nr] = bv.x; Bs[kc + 1][nr] = bv.y;
            Bs[kc + 2][nr] = bv.z; Bs[kc + 3][nr] = bv.w;
        } else {
            int kr = tid >> 5, nc = (tid & 31) << 2;
            float4 bv = make_float4(0.f, 0.f, 0.f, 0.f);
            int ncol = bn + nc;
            if (ncol < N)  // N%4==0 in all uses -> whole float4 in range
                bv = *reinterpret_cast<const float4*>(B + (size_t)(k0 + kr) * N + ncol);
            Bs[kr][nc + 0] = bv.x; Bs[kr][nc + 1] = bv.y;
            Bs[kr][nc + 2] = bv.z; Bs[kr][nc + 3] = bv.w;
        }
        __syncthreads();
#pragma unroll
        for (int k = 0; k < BK; k++) {
            float4 a0 = *reinterpret_cast<const float4*>(&As[k][ty * 8]);
            float4 a1 = *reinterpret_cast<const float4*>(&As[k][ty * 8 + 4]);
            float4 b0 = *reinterpret_cast<const float4*>(&Bs[k][tx * 8]);
            float4 b1 = *reinterpret_cast<const float4*>(&Bs[k][tx * 8 + 4]);
            float a[8] = {a0.x, a0.y, a0.z, a0.w, a1.x, a1.y, a1.z, a1.w};
            float b[8] = {b0.x, b0.y, b0.z, b0.w, b1.x, b1.y, b1.z, b1.w};
#pragma unroll
            for (int i = 0; i < 8; i++)
#pragma unroll
                for (int j = 0; j < 8; j++) acc[i][j] += a[i] * b[j];
        }
        __syncthreads();
    }
#pragma unroll
    for (int i = 0; i < 8; i++) {
        int row = bm + ty * 8 + i;
        if (row >= M) continue;
        float* Cr = C + (size_t)row * N;
#pragma unroll
        for (int j = 0; j < 8; j++) {
            int col = bn + tx * 8 + j;
            if (col < N) {
                float val = acc[i][j];
                if (BIAS) val += bias[col];
                Cr[col] = val;
            }
        }
    }
}

static inline dim3 gemm_grid(int M, int N) {
    return dim3((unsigned)((N + BN - 1) / BN), (unsigned)((M + BM - 1) / BM));
}

// ------------------------- launch ---------------------------------------------
extern "C" void kernel_launch(void* const* d_in, const int* in_sizes, int n_in,
                              void* d_out, int out_size) {
    (void)in_sizes; (void)n_in; (void)out_size;
    const int*   x    = (const int*)  d_in[0];
    const int*   eidx = (const int*)  d_in[1];
    const int*   et   = (const int*)  d_in[2];
    const float* emb  = (const float*)d_in[3];
    const float* rel1 = (const float*)d_in[4];
    // Wr1 (d_in[5]) / br1 (d_in[6]) unused: layer-1 rels are discarded
    const float* Wn1  = (const float*)d_in[7];
    const float* bn1  = (const float*)d_in[8];
    const float* cw1  = (const float*)d_in[9];
    const float* gm1  = (const float*)d_in[10];
    const float* bt1  = (const float*)d_in[11];
    const float* rel2 = (const float*)d_in[12];
    const float* Wr2  = (const float*)d_in[13];
    const float* br2  = (const float*)d_in[14];
    const float* Wn2  = (const float*)d_in[15];
    const float* bn2  = (const float*)d_in[16];
    const float* cw2  = (const float*)d_in[17];
    const float* gm2  = (const float*)d_in[18];
    const float* bt2  = (const float*)d_in[19];

    float* out_h    = (float*)d_out;
    float* out_rels = out_h + (size_t)N_NODES * DIM;
    const int* src = eidx;
    const int* dst = eidx + N_EDGES;

    float *pH, *pHS, *pRS, *pAGG, *pOUT, *pBf, *pJ, *pMw, *pW;
    cudaGetSymbolAddress((void**)&pH,   g_h);
    cudaGetSymbolAddress((void**)&pHS,  g_HS);
    cudaGetSymbolAddress((void**)&pRS,  g_RS);
    cudaGetSymbolAddress((void**)&pAGG, g_AGG);
    cudaGetSymbolAddress((void**)&pOUT, g_OUT);
    cudaGetSymbolAddress((void**)&pBf,  g_Bf);
    cudaGetSymbolAddress((void**)&pJ,   g_J);
    cudaGetSymbolAddress((void**)&pMw,  g_Mw);
    cudaGetSymbolAddress((void**)&pW,   g_w);

    build_bf_kernel<<<(DIM * SPEC_PAD + 255) / 256, 256>>>(pBf);
    build_j_kernel<<<(258 * DIM + 255) / 256, 256>>>(pJ);
    softmax_kernel<<<1, 32>>>(cw1, cw2, pW);
    gather_kernel<<<(N_NODES * (DIM / 4) + 255) / 256, 256>>>(x, emb, pH);

    const int warps_nodes = (N_NODES * 32 + 255) / 256;
    const int warps_edges = (N_EDGES * 32 + 255) / 256;

    for (int L = 0; L < 2; L++) {
        const float* rel = (L == 0) ? rel1 : rel2;
        const float* Wn  = (L == 0) ? Wn1  : Wn2;
        const float* bn  = (L == 0) ? bn1  : bn2;
        const float* gm  = (L == 0) ? gm1  : gm2;
        const float* bt  = (L == 0) ? bt1  : bt2;
        float* hout      = (L == 0) ? pH   : out_h;

        // forward DFT of h and rel tables
        sgemm_kernel<false, false><<<gemm_grid(N_NODES, SPEC_PAD), 256>>>(
            pH, pBf, pHS, nullptr, N_NODES, SPEC_PAD, DIM);
        sgemm_kernel<false, false><<<gemm_grid(NRELS, SPEC_PAD), 256>>>(
            rel, pBf, pRS, nullptr, NRELS, SPEC_PAD, DIM);
        // combined weight Mw = [Wn^T ; J @ Wn^T ; 0]
        prep_mw_kernel<<<(AGGW * DIM + 255) / 256, 256>>>(Wn, pMw);
        sgemm_kernel<true, false><<<gemm_grid(258, DIM), 256>>>(
            pJ, Wn, pMw + (size_t)DIM * DIM, nullptr, 258, DIM, DIM);
        // self-loop init + edge scatter
        node_init_kernel<<<warps_nodes, 256>>>(pH, pHS, rel, pRS, pW, 3 * L, pAGG);
        edge_kernel<<<warps_edges, 256>>>(src, dst, et, pH, pHS, rel, pRS, pW, 3 * L, pAGG);
        // node linear (with fused inverse rfft)
        sgemm_kernel<false, false><<<gemm_grid(N_NODES, DIM), 256>>>(
            pAGG, pMw, pOUT, nullptr, N_NODES, DIM, AGGW);
        // residual + LN + ReLU
        epilogue_kernel<<<warps_nodes, 256>>>(pOUT, pH, bn, gm, bt, hout);
    }

    // rels = rel_emb2 @ Wr2^T + br2
    sgemm_kernel<true, true><<<gemm_grid(NRELS, DIM), 256>>>(
        rel2, Wr2, out_rels, br2, NRELS, DIM, DIM);
}

// round 2
// speedup vs baseline: 1.9238x; 1.9238x over previous
#include <cuda_runtime.h>
#include <math.h>
#include <stdint.h>

#define N_NODES 50000
#define N_EDGES 250000
#define DIM     256
#define NRELS   400
#define SPEC_PAD 260     // 258 floats (129 complex bins) + 2 pad -> 16B rows
#define AGGW    520      // 256 time + 258 spectral + 6 pad -> 16B rows
#define LN_EPS  1e-5f

// ------------------------- scratch (device globals) --------------------------
__device__ float g_h  [(size_t)N_NODES * DIM];       // current node features
__device__ float g_HS [(size_t)N_NODES * SPEC_PAD];  // rfft(h)
__device__ float g_RS [(size_t)NRELS   * SPEC_PAD];  // rfft(rel)
__device__ float g_AGG[(size_t)N_NODES * AGGW];      // [aggT(256) | aggF(258) | pad]
__device__ float g_HC [(size_t)N_NODES * DIM];       // aggT + irfft(aggF)
__device__ float g_OUT[(size_t)N_NODES * DIM];
__device__ float g_tw [7 * 64 * 2];                  // stage twiddles (cos, +sin)
__device__ float g_wt [129 * 2];                     // untangle W^k = exp(-i pi k/128)
__device__ float g_wi [129 * 2];                     // inverse  W^-k = exp(+i pi k/128)
__device__ float g_w  [6];                           // softmax(cw1), softmax(cw2)

// ------------------------- small helpers -------------------------------------
__device__ __forceinline__ float2 cmulf(float2 a, float2 b) {
    return make_float2(a.x * b.x - a.y * b.y, a.x * b.y + a.y * b.x);
}
__device__ __forceinline__ void red_add_v4(float* p, float4 v) {
    asm volatile("red.global.add.v4.f32 [%0], {%1,%2,%3,%4};"
                 :: "l"(p), "f"(v.x), "f"(v.y), "f"(v.z), "f"(v.w) : "memory");
}
__device__ __forceinline__ void red_add_v2(float* p, float2 v) {
    asm volatile("red.global.add.v2.f32 [%0], {%1,%2};"
                 :: "l"(p), "f"(v.x), "f"(v.y) : "memory");
}

// ------------------------- table builders (fp64 accuracy) --------------------
__global__ void build_tw_kernel(float* tw, float* wt, float* wi) {
    int i = blockIdx.x * blockDim.x + threadIdx.x;
    if (i < 7 * 64) {
        int s = i >> 6, j = i & 63;
        int l = 64 >> s;
        float2 v = make_float2(0.f, 0.f);
        if (j < l) {
            double a = (double)j / (double)l;
            v = make_float2((float)cospi(a), (float)sinpi(a));
        }
        reinterpret_cast<float2*>(tw)[i] = v;
    }
    if (i < 129) {
        double a = (double)i / 128.0;
        reinterpret_cast<float2*>(wt)[i] = make_float2((float)cospi(a), (float)(-sinpi(a)));
        reinterpret_cast<float2*>(wi)[i] = make_float2((float)cospi(a), (float)( sinpi(a)));
    }
}

__global__ void softmax_kernel(const float* __restrict__ cw1,
                               const float* __restrict__ cw2,
                               float* __restrict__ w) {
    if (threadIdx.x == 0 && blockIdx.x == 0) {
        for (int L = 0; L < 2; L++) {
            const float* c = (L == 0) ? cw1 : cw2;
            float m = fmaxf(c[0], fmaxf(c[1], c[2]));
            float e0 = expf(c[0] - m), e1 = expf(c[1] - m), e2 = expf(c[2] - m);
            float s = e0 + e1 + e2;
            w[L * 3 + 0] = e0 / s; w[L * 3 + 1] = e1 / s; w[L * 3 + 2] = e2 / s;
        }
    }
}

// ------------------------- gather h = emb[x] ---------------------------------
__global__ void gather_kernel(const int* __restrict__ x,
                              const float* __restrict__ emb,
                              float* __restrict__ h) {
    int i = blockIdx.x * blockDim.x + threadIdx.x;
    if (i >= N_NODES * (DIM / 4)) return;
    int v = i >> 6, c = i & 63;
    reinterpret_cast<float4*>(h)[(size_t)v * 64 + c] =
        reinterpret_cast<const float4*>(emb)[(size_t)x[v] * 64 + c];
}

// ------------------------- 128-pt Stockham FFT (64 threads/row) --------------
// Natural order in/out. Result lands in buffer b1. sgn=-1: forward, +1: inverse
// (unnormalized). Twiddle table tw holds (cos, sin) per (stage, j).
__device__ __forceinline__ void fft128(float2* b0, float2* b1, int t, float sgn,
                                       const float2* __restrict__ tw) {
    float2* src = b0;
    float2* dst = b1;
#pragma unroll
    for (int s = 0; s < 7; s++) {
        int m = 1 << s;
        int j = t >> s;
        float2 w = tw[(s << 6) + j];
        w.y *= sgn;
        float2 c0 = src[t];
        float2 c1 = src[t + 64];
        float2 sum = make_float2(c0.x + c1.x, c0.y + c1.y);
        float2 d   = make_float2(c0.x - c1.x, c0.y - c1.y);
        int idx = (t & (m - 1)) | ((t >> s) << (s + 1));
        dst[idx]     = sum;
        dst[idx + m] = cmulf(d, w);
        float2* tmp = src; src = dst; dst = tmp;
        __syncthreads();
    }
}

// ------------------------- forward rfft: X[row,256] -> S[row, 258(+2)] -------
__global__ __launch_bounds__(256)
void fwd_rfft_kernel(const float* __restrict__ X, float* __restrict__ S,
                     const float2* __restrict__ tw, const float2* __restrict__ wt) {
    __shared__ float2 buf[4][2][128];
    int g = threadIdx.x >> 6, t = threadIdx.x & 63;
    int row = (blockIdx.x << 2) + g;
    float4 v = reinterpret_cast<const float4*>(X + (size_t)row * DIM)[t];
    buf[g][0][2 * t]     = make_float2(v.x, v.y);   // z[n] = x[2n] + i x[2n+1]
    buf[g][0][2 * t + 1] = make_float2(v.z, v.w);
    __syncthreads();
    fft128(buf[g][0], buf[g][1], t, -1.f, tw);
    float2* Z = buf[g][1];
    float* Srow = S + (size_t)row * SPEC_PAD;
#pragma unroll
    for (int u = 0; u < 2; u++) {
        int k = t + 64 * u;                          // 0..127
        float2 Zk = Z[k];
        float2 Zm = Z[(128 - k) & 127];
        float2 Ze = make_float2(0.5f * (Zk.x + Zm.x), 0.5f * (Zk.y - Zm.y));
        float2 d  = make_float2(Zk.x - Zm.x, Zk.y + Zm.y);   // Z[k] - conj(Z[128-k])
        float2 Zo = make_float2(0.5f * d.y, -0.5f * d.x);    // -i/2 * d
        float2 W  = wt[k];
        float2 H  = make_float2(Ze.x + W.x * Zo.x - W.y * Zo.y,
                                Ze.y + W.x * Zo.y + W.y * Zo.x);
        *reinterpret_cast<float2*>(Srow + 2 * k) = H;
    }
    if (t == 0) {  // bin 128: Re Z0 - Im Z0, imag exactly 0
        float2 Z0 = Z[0];
        *reinterpret_cast<float2*>(Srow + 256) = make_float2(Z0.x - Z0.y, 0.f);
    }
}

// ------------------------- inverse: HC = aggT + irfft(aggF) ------------------
__global__ __launch_bounds__(256)
void inv_rfft_kernel(const float* __restrict__ AGG, float* __restrict__ HC,
                     const float2* __restrict__ tw, const float2* __restrict__ wi) {
    __shared__ float2 buf[4][2][128];
    __shared__ float2 sA[4][132];
    int g = threadIdx.x >> 6, t = threadIdx.x & 63;
    int row = (blockIdx.x << 2) + g;
    const float* aggr = AGG + (size_t)row * AGGW;
    const float2* A = reinterpret_cast<const float2*>(aggr + DIM);
    sA[g][t] = A[t];
    sA[g][t + 64] = A[t + 64];
    if (t == 0) sA[g][128] = A[128];
    __syncthreads();
#pragma unroll
    for (int u = 0; u < 2; u++) {
        int k = t + 64 * u;                          // 0..127
        float2 Ak = sA[g][k], Am = sA[g][128 - k];
        float2 Ze = make_float2(0.5f * (Ak.x + Am.x), 0.5f * (Ak.y - Am.y));
        float2 hd = make_float2(0.5f * (Ak.x - Am.x), 0.5f * (Ak.y + Am.y));
        float2 Zo = cmulf(wi[k], hd);                // W^{-k} * (A[k]-conj(A[128-k]))/2
        buf[g][0][k] = make_float2(Ze.x - Zo.y, Ze.y + Zo.x);  // Ze + i Zo
    }
    __syncthreads();
    fft128(buf[g][0], buf[g][1], t, +1.f, tw);
    float2* z = buf[g][1];
    float4 base = reinterpret_cast<const float4*>(aggr)[t];
    float2 z0 = z[2 * t], z1 = z[2 * t + 1];
    const float inv = 1.f / 128.f;
    float4 o = make_float4(base.x + z0.x * inv, base.y + z0.y * inv,
                           base.z + z1.x * inv, base.w + z1.y * inv);
    reinterpret_cast<float4*>(HC + (size_t)row * DIM)[t] = o;
}

// ------------------------- self-loop init (writes AGG) -----------------------
__global__ void node_init_kernel(const float* __restrict__ h,
                                 const float* __restrict__ HS,
                                 const float* __restrict__ rel,
                                 const float* __restrict__ RS,
                                 const float* __restrict__ w, int wofs,
                                 float* __restrict__ AGG) {
    int v = (blockIdx.x * blockDim.x + threadIdx.x) >> 5;
    if (v >= N_NODES) return;
    int lane = threadIdx.x & 31;
    float w0 = w[wofs + 0], w1 = w[wofs + 1], w2 = w[wofs + 2];
    const float4* hv = reinterpret_cast<const float4*>(h + (size_t)v * DIM);
    const float4* r0 = reinterpret_cast<const float4*>(rel);          // rel row 0
    float* aggT = AGG + (size_t)v * AGGW;
#pragma unroll
    for (int i = 0; i < 2; i++) {
        int c = lane + 32 * i;
        float4 a = hv[c], b = r0[c];
        float4 m = make_float4(w0 * a.x * b.x + w1 * (a.x + b.x),
                               w0 * a.y * b.y + w1 * (a.y + b.y),
                               w0 * a.z * b.z + w1 * (a.z + b.z),
                               w0 * a.w * b.w + w1 * (a.w + b.w));
        reinterpret_cast<float4*>(aggT)[c] = m;
    }
    const float4* Hs = reinterpret_cast<const float4*>(HS + (size_t)v * SPEC_PAD);
    const float4* Rt = reinterpret_cast<const float4*>(RS);           // RS row 0
    float* aggF = aggT + DIM;
#pragma unroll
    for (int i = 0; i < 2; i++) {
        int c = lane + 32 * i;                      // bins 2c, 2c+1
        float4 a = Hs[c], b = Rt[c];
        float4 m = make_float4(w2 * (a.x * b.x + a.y * b.y),
                               w2 * (a.y * b.x - a.x * b.y),
                               w2 * (a.z * b.z + a.w * b.w),
                               w2 * (a.w * b.z - a.z * b.w));
        reinterpret_cast<float4*>(aggF)[c] = m;
    }
    if (lane == 0) {
        float2 a = *reinterpret_cast<const float2*>(HS + (size_t)v * SPEC_PAD + 256);
        float2 b = *reinterpret_cast<const float2*>(RS + 256);
        *reinterpret_cast<float2*>(aggF + 256) =
            make_float2(w2 * (a.x * b.x + a.y * b.y), w2 * (a.y * b.x - a.x * b.y));
    }
}

// ------------------------- edge scatter (vector reds) ------------------------
__global__ void edge_kernel(const int* __restrict__ src,
                            const int* __restrict__ dst,
                            const int* __restrict__ et,
                            const float* __restrict__ h,
                            const float* __restrict__ HS,
                            const float* __restrict__ rel,
                            const float* __restrict__ RS,
                            const float* __restrict__ w, int wofs,
                            float* __restrict__ AGG) {
    int e = (blockIdx.x * blockDim.x + threadIdx.x) >> 5;
    if (e >= N_EDGES) return;
    int lane = threadIdx.x & 31;
    int s = src[e], v = dst[e], t = et[e];
    float w0 = w[wofs + 0], w1 = w[wofs + 1], w2 = w[wofs + 2];
    const float4* hs = reinterpret_cast<const float4*>(h   + (size_t)s * DIM);
    const float4* rt = reinterpret_cast<const float4*>(rel + (size_t)t * DIM);
    float* aggT = AGG + (size_t)v * AGGW;
#pragma unroll
    for (int i = 0; i < 2; i++) {
        int c = lane + 32 * i;
        float4 a = hs[c], b = rt[c];
        float4 m = make_float4(w0 * a.x * b.x + w1 * (a.x + b.x),
                               w0 * a.y * b.y + w1 * (a.y + b.y),
                               w0 * a.z * b.z + w1 * (a.z + b.z),
                               w0 * a.w * b.w + w1 * (a.w + b.w));
        red_add_v4(aggT + 4 * c, m);
    }
    const float4* Hs = reinterpret_cast<const float4*>(HS + (size_t)s * SPEC_PAD);
    const float4* Rt = reinterpret_cast<const float4*>(RS + (size_t)t * SPEC_PAD);
    float* aggF = aggT + DIM;
#pragma unroll
    for (int i = 0; i < 2; i++) {
        int c = lane + 32 * i;                      // bins 2c, 2c+1
        float4 a = Hs[c], b = Rt[c];
        float4 m = make_float4(w2 * (a.x * b.x + a.y * b.y),
                               w2 * (a.y * b.x - a.x * b.y),
                               w2 * (a.z * b.z + a.w * b.w),
                               w2 * (a.w * b.z - a.z * b.w));
        red_add_v4(aggF + 4 * c, m);
    }
    if (lane == 0) {                                // bin 128
        float2 a = *reinterpret_cast<const float2*>(HS + (size_t)s * SPEC_PAD + 256);
        float2 b = *reinterpret_cast<const float2*>(RS + (size_t)t * SPEC_PAD + 256);
        red_add_v2(aggF + 256,
                   make_float2(w2 * (a.x * b.x + a.y * b.y),
                               w2 * (a.y * b.x - a.x * b.y)));
    }
}

// ------------------------- residual + LayerNorm + ReLU -----------------------
__global__ void epilogue_kernel(const float* __restrict__ OUT,
                                const float* __restrict__ h_in,
                                const float* __restrict__ bn,
                                const float* __restrict__ gamma,
                                const float* __restrict__ beta,
                                float* __restrict__ h_out) {
    int v = (blockIdx.x * blockDim.x + threadIdx.x) >> 5;
    if (v >= N_NODES) return;
    int lane = threadIdx.x & 31;
    const float* o  = OUT  + (size_t)v * DIM;
    const float* hi = h_in + (size_t)v * DIM;
    float z[8];
    float s = 0.f;
#pragma unroll
    for (int i = 0; i < 8; i++) {
        int d = lane + 32 * i;
        z[i] = o[d] + bn[d] + hi[d];
        s += z[i];
    }
#pragma unroll
    for (int off = 16; off; off >>= 1) s += __shfl_xor_sync(0xffffffffu, s, off);
    float mu = s * (1.f / DIM);
    float vv = 0.f;
#pragma unroll
    for (int i = 0; i < 8; i++) { float t = z[i] - mu; vv += t * t; }
#pragma unroll
    for (int off = 16; off; off >>= 1) vv += __shfl_xor_sync(0xffffffffu, vv, off);
    float rstd = rsqrtf(vv * (1.f / DIM) + LN_EPS);
    float* ho = h_out + (size_t)v * DIM;
#pragma unroll
    for (int i = 0; i < 8; i++) {
        int d = lane + 32 * i;
        float y = (z[i] - mu) * rstd * gamma[d] + beta[d];
        ho[d] = fmaxf(y, 0.f);
    }
}

// ------------------------- fp32 SGEMM: C = A @ (TB ? B^T : B) (+bias) --------
#define BM 128
#define BN 128
#define BK 8

template<bool TB, bool BIAS>
__global__ __launch_bounds__(256)
void sgemm_kernel(const float* __restrict__ A, const float* __restrict__ B,
                  float* __restrict__ C, const float* __restrict__ bias,
                  int M, int N, int K) {
    __shared__ __align__(16) float As[BK][BM];
    __shared__ __align__(16) float Bs[BK][BN];
    int tid = threadIdx.x;
    int tx = tid & 15, ty = tid >> 4;
    int bm = blockIdx.y * BM, bn = blockIdx.x * BN;

    int ar = tid >> 1;
    int ac = (tid & 1) << 2;
    float acc[8][8];
#pragma unroll
    for (int i = 0; i < 8; i++)
#pragma unroll
        for (int j = 0; j < 8; j++) acc[i][j] = 0.f;

    for (int k0 = 0; k0 < K; k0 += BK) {
        float4 av = make_float4(0.f, 0.f, 0.f, 0.f);
        int arow = bm + ar;
        if (arow < M)
            av = *reinterpret_cast<const float4*>(A + (size_t)arow * K + k0 + ac);
        As[ac + 0][ar] = av.x; As[ac + 1][ar] = av.y;
        As[ac + 2][ar] = av.z; As[ac + 3][ar] = av.w;
        if (TB) {
            int nr = tid >> 1, kc = (tid & 1) << 2;
            float4 bv = make_float4(0.f, 0.f, 0.f, 0.f);
            int nrow = bn + nr;
            if (nrow < N)
                bv = *reinterpret_cast<const float4*>(B + (size_t)nrow * K + k0 + kc);
            Bs[kc + 0][nr] = bv.x; Bs[kc + 1][nr] = bv.y;
            Bs[kc + 2][nr] = bv.z; Bs[kc + 3][nr] = bv.w;
        } else {
            int kr = tid >> 5, nc = (tid & 31) << 2;
            float4 bv = make_float4(0.f, 0.f, 0.f, 0.f);
            int ncol = bn + nc;
            if (ncol < N)
                bv = *reinterpret_cast<const float4*>(B + (size_t)(k0 + kr) * N + ncol);
            Bs[kr][nc + 0] = bv.x; Bs[kr][nc + 1] = bv.y;
            Bs[kr][nc + 2] = bv.z; Bs[kr][nc + 3] = bv.w;
        }
        __syncthreads();
#pragma unroll
        for (int k = 0; k < BK; k++) {
            float4 a0 = *reinterpret_cast<const float4*>(&As[k][ty * 8]);
            float4 a1 = *reinterpret_cast<const float4*>(&As[k][ty * 8 + 4]);
            float4 b0 = *reinterpret_cast<const float4*>(&Bs[k][tx * 8]);
            float4 b1 = *reinterpret_cast<const float4*>(&Bs[k][tx * 8 + 4]);
            float a[8] = {a0.x, a0.y, a0.z, a0.w, a1.x, a1.y, a1.z, a1.w};
            float b[8] = {b0.x, b0.y, b0.z, b0.w, b1.x, b1.y, b1.z, b1.w};
#pragma unroll
            for (int i = 0; i < 8; i++)
#pragma unroll
                for (int j = 0; j < 8; j++) acc[i][j] += a[i] * b[j];
        }
        __syncthreads();
    }
#pragma unroll
    for (int i = 0; i < 8; i++) {
        int row = bm + ty * 8 + i;
        if (row >= M) continue;
        float* Cr = C + (size_t)row * N;
#pragma unroll
        for (int j = 0; j < 8; j++) {
            int col = bn + tx * 8 + j;
            if (col < N) {
                float val = acc[i][j];
                if (BIAS) val += bias[col];
                Cr[col] = val;
            }
        }
    }
}

static inline dim3 gemm_grid(int M, int N) {
    return dim3((unsigned)((N + BN - 1) / BN), (unsigned)((M + BM - 1) / BM));
}

// ------------------------- launch --------------------------------------------
extern "C" void kernel_launch(void* const* d_in, const int* in_sizes, int n_in,
                              void* d_out, int out_size) {
    (void)in_sizes; (void)n_in; (void)out_size;
    const int*   x    = (const int*)  d_in[0];
    const int*   eidx = (const int*)  d_in[1];
    const int*   et   = (const int*)  d_in[2];
    const float* emb  = (const float*)d_in[3];
    const float* rel1 = (const float*)d_in[4];
    const float* Wn1  = (const float*)d_in[7];
    const float* bn1  = (const float*)d_in[8];
    const float* cw1  = (const float*)d_in[9];
    const float* gm1  = (const float*)d_in[10];
    const float* bt1  = (const float*)d_in[11];
    const float* rel2 = (const float*)d_in[12];
    const float* Wr2  = (const float*)d_in[13];
    const float* br2  = (const float*)d_in[14];
    const float* Wn2  = (const float*)d_in[15];
    const float* bn2  = (const float*)d_in[16];
    const float* cw2  = (const float*)d_in[17];
    const float* gm2  = (const float*)d_in[18];
    const float* bt2  = (const float*)d_in[19];

    float* out_h    = (float*)d_out;
    float* out_rels = out_h + (size_t)N_NODES * DIM;
    const int* src = eidx;
    const int* dst = eidx + N_EDGES;

    float *pH, *pHS, *pRS, *pAGG, *pHC, *pOUT, *pTw, *pWt, *pWi, *pW;
    cudaGetSymbolAddress((void**)&pH,   g_h);
    cudaGetSymbolAddress((void**)&pHS,  g_HS);
    cudaGetSymbolAddress((void**)&pRS,  g_RS);
    cudaGetSymbolAddress((void**)&pAGG, g_AGG);
    cudaGetSymbolAddress((void**)&pHC,  g_HC);
    cudaGetSymbolAddress((void**)&pOUT, g_OUT);
    cudaGetSymbolAddress((void**)&pTw,  g_tw);
    cudaGetSymbolAddress((void**)&pWt,  g_wt);
    cudaGetSymbolAddress((void**)&pWi,  g_wi);
    cudaGetSymbolAddress((void**)&pW,   g_w);

    const float2* tw = (const float2*)pTw;
    const float2* wt = (const float2*)pWt;
    const float2* wi = (const float2*)pWi;

    build_tw_kernel<<<2, 256>>>(pTw, pWt, pWi);
    softmax_kernel<<<1, 32>>>(cw1, cw2, pW);
    gather_kernel<<<(N_NODES * (DIM / 4) + 255) / 256, 256>>>(x, emb, pH);

    const int warps_nodes = (N_NODES * 32 + 255) / 256;
    const int warps_edges = (N_EDGES * 32 + 255) / 256;

    for (int L = 0; L < 2; L++) {
        const float* rel = (L == 0) ? rel1 : rel2;
        const float* Wn  = (L == 0) ? Wn1  : Wn2;
        const float* bn  = (L == 0) ? bn1  : bn2;
        const float* gm  = (L == 0) ? gm1  : gm2;
        const float* bt  = (L == 0) ? bt1  : bt2;
        float* hout      = (L == 0) ? pH   : out_h;

        // forward rFFT of h (50000 rows) and rel table (400 rows)
        fwd_rfft_kernel<<<N_NODES / 4, 256>>>(pH, pHS, tw, wt);
        fwd_rfft_kernel<<<NRELS / 4, 256>>>(rel, pRS, tw, wt);
        // self-loop init + edge scatter (vector reductions)
        node_init_kernel<<<warps_nodes, 256>>>(pH, pHS, rel, pRS, pW, 3 * L, pAGG);
        edge_kernel<<<warps_edges, 256>>>(src, dst, et, pH, pHS, rel, pRS, pW, 3 * L, pAGG);
        // inverse rFFT fused with time-domain aggregate -> HC [N, 256]
        inv_rfft_kernel<<<N_NODES / 4, 256>>>(pAGG, pHC, tw, wi);
        // node linear: OUT = HC @ Wn^T
        sgemm_kernel<true, false><<<gemm_grid(N_NODES, DIM), 256>>>(
            pHC, Wn, pOUT, nullptr, N_NODES, DIM, DIM);
        // residual + LN + ReLU
        epilogue_kernel<<<warps_nodes, 256>>>(pOUT, pH, bn, gm, bt, hout);
    }

    // rels = rel_emb2 @ Wr2^T + br2
    sgemm_kernel<true, true><<<gemm_grid(NRELS, DIM), 256>>>(
        rel2, Wr2, out_rels, br2, NRELS, DIM, DIM);
}

// round 3
// speedup vs baseline: 2.3653x; 1.2295x over previous
#include <cuda_runtime.h>
#include <cuda_bf16.h>
#include <math.h>
#include <stdint.h>

#define N_NODES 50000
#define N_EDGES 250000
#define DIM     256
#define NRELS   400
#define SPEC_PAD 260     // 258 floats (129 complex bins) + 2 pad -> 16B rows
#define AGGW    520      // 256 time + 258 spectral + 6 pad
#define LN_EPS  1e-5f

// ------------------------- scratch (device globals) --------------------------
__device__ float g_h  [(size_t)N_NODES * DIM];
__device__ float g_HS [(size_t)N_NODES * SPEC_PAD];
__device__ float g_RS [(size_t)NRELS   * SPEC_PAD];
__device__ float g_AGG[(size_t)N_NODES * AGGW];
__device__ float g_HC [(size_t)N_NODES * DIM];
__device__ float g_OUT[(size_t)N_NODES * DIM];
__device__ float g_tw [7 * 64 * 2];
__device__ float g_wt [129 * 2];
__device__ float g_wi [129 * 2];
__device__ float g_w  [6];
__device__ int   g_deg[N_NODES];
__device__ int   g_off[N_NODES + 1];
__device__ int   g_pos[N_NODES];
__device__ int2  g_edges[N_EDGES];     // (src, et) sorted by dst

// ------------------------- small helpers -------------------------------------
__device__ __forceinline__ float2 cmulf(float2 a, float2 b) {
    return make_float2(a.x * b.x - a.y * b.y, a.x * b.y + a.y * b.x);
}

// ------------------------- table builders (fp64 accuracy) --------------------
__global__ void build_tw_kernel(float* tw, float* wt, float* wi) {
    int i = blockIdx.x * blockDim.x + threadIdx.x;
    if (i < 7 * 64) {
        int s = i >> 6, j = i & 63;
        int l = 64 >> s;
        float2 v = make_float2(0.f, 0.f);
        if (j < l) {
            double a = (double)j / (double)l;
            v = make_float2((float)cospi(a), (float)sinpi(a));
        }
        reinterpret_cast<float2*>(tw)[i] = v;
    }
    if (i < 129) {
        double a = (double)i / 128.0;
        reinterpret_cast<float2*>(wt)[i] = make_float2((float)cospi(a), (float)(-sinpi(a)));
        reinterpret_cast<float2*>(wi)[i] = make_float2((float)cospi(a), (float)( sinpi(a)));
    }
}

__global__ void softmax_kernel(const float* __restrict__ cw1,
                               const float* __restrict__ cw2,
                               float* __restrict__ w) {
    if (threadIdx.x == 0 && blockIdx.x == 0) {
        for (int L = 0; L < 2; L++) {
            const float* c = (L == 0) ? cw1 : cw2;
            float m = fmaxf(c[0], fmaxf(c[1], c[2]));
            float e0 = expf(c[0] - m), e1 = expf(c[1] - m), e2 = expf(c[2] - m);
            float s = e0 + e1 + e2;
            w[L * 3 + 0] = e0 / s; w[L * 3 + 1] = e1 / s; w[L * 3 + 2] = e2 / s;
        }
    }
}

// ------------------------- gather h = emb[x] ---------------------------------
__global__ void gather_kernel(const int* __restrict__ x,
                              const float* __restrict__ emb,
                              float* __restrict__ h) {
    int i = blockIdx.x * blockDim.x + threadIdx.x;
    if (i >= N_NODES * (DIM / 4)) return;
    int v = i >> 6, c = i & 63;
    reinterpret_cast<float4*>(h)[(size_t)v * 64 + c] =
        reinterpret_cast<const float4*>(emb)[(size_t)x[v] * 64 + c];
}

// ------------------------- edge sorting (counting sort by dst) ---------------
__global__ void zero_deg_kernel(int* deg) {
    int i = blockIdx.x * blockDim.x + threadIdx.x;
    if (i < N_NODES) deg[i] = 0;
}
__global__ void hist_kernel(const int* __restrict__ dst, int* deg) {
    int e = blockIdx.x * blockDim.x + threadIdx.x;
    if (e < N_EDGES) atomicAdd(&deg[dst[e]], 1);
}
__global__ __launch_bounds__(1024)
void scan_kernel(const int* __restrict__ deg, int* off, int* pos) {
    __shared__ int ps[1024];
    int t = threadIdx.x;
    const int CH = (N_NODES + 1023) / 1024;     // 49
    int b0 = t * CH, b1 = min(b0 + CH, N_NODES);
    int s = 0;
    for (int i = b0; i < b1; i++) s += deg[i];
    ps[t] = s;
    __syncthreads();
    for (int o = 1; o < 1024; o <<= 1) {
        int u = (t >= o) ? ps[t - o] : 0;
        __syncthreads();
        ps[t] += u;
        __syncthreads();
    }
    int run = ps[t] - s;                         // exclusive prefix
    for (int i = b0; i < b1; i++) {
        off[i] = run; pos[i] = run; run += deg[i];
    }
    if (t == 1023) off[N_NODES] = ps[1023];
}
__global__ void scatter_kernel(const int* __restrict__ src,
                               const int* __restrict__ dst,
                               const int* __restrict__ et,
                               int* pos, int2* edges) {
    int e = blockIdx.x * blockDim.x + threadIdx.x;
    if (e >= N_EDGES) return;
    int p = atomicAdd(&pos[dst[e]], 1);
    edges[p] = make_int2(src[e], et[e]);
}

// ------------------------- 128-pt Stockham FFT (64 threads/row) --------------
__device__ __forceinline__ void fft128(float2* b0, float2* b1, int t, float sgn,
                                       const float2* __restrict__ tw) {
    float2* src = b0;
    float2* dst = b1;
#pragma unroll
    for (int s = 0; s < 7; s++) {
        int m = 1 << s;
        int j = t >> s;
        float2 w = tw[(s << 6) + j];
        w.y *= sgn;
        float2 c0 = src[t];
        float2 c1 = src[t + 64];
        float2 sum = make_float2(c0.x + c1.x, c0.y + c1.y);
        float2 d   = make_float2(c0.x - c1.x, c0.y - c1.y);
        int idx = (t & (m - 1)) | ((t >> s) << (s + 1));
        dst[idx]     = sum;
        dst[idx + m] = cmulf(d, w);
        float2* tmp = src; src = dst; dst = tmp;
        __syncthreads();
    }
}

// ------------------------- forward rfft --------------------------------------
__global__ __launch_bounds__(256)
void fwd_rfft_kernel(const float* __restrict__ X, float* __restrict__ S,
                     const float2* __restrict__ tw, const float2* __restrict__ wt) {
    __shared__ float2 buf[4][2][128];
    int g = threadIdx.x >> 6, t = threadIdx.x & 63;
    int row = (blockIdx.x << 2) + g;
    float4 v = reinterpret_cast<const float4*>(X + (size_t)row * DIM)[t];
    buf[g][0][2 * t]     = make_float2(v.x, v.y);
    buf[g][0][2 * t + 1] = make_float2(v.z, v.w);
    __syncthreads();
    fft128(buf[g][0], buf[g][1], t, -1.f, tw);
    float2* Z = buf[g][1];
    float* Srow = S + (size_t)row * SPEC_PAD;
#pragma unroll
    for (int u = 0; u < 2; u++) {
        int k = t + 64 * u;
        float2 Zk = Z[k];
        float2 Zm = Z[(128 - k) & 127];
        float2 Ze = make_float2(0.5f * (Zk.x + Zm.x), 0.5f * (Zk.y - Zm.y));
        float2 d  = make_float2(Zk.x - Zm.x, Zk.y + Zm.y);
        float2 Zo = make_float2(0.5f * d.y, -0.5f * d.x);
        float2 W  = wt[k];
        float2 H  = make_float2(Ze.x + W.x * Zo.x - W.y * Zo.y,
                                Ze.y + W.x * Zo.y + W.y * Zo.x);
        *reinterpret_cast<float2*>(Srow + 2 * k) = H;
    }
    if (t == 0) {
        float2 Z0 = Z[0];
        *reinterpret_cast<float2*>(Srow + 256) = make_float2(Z0.x - Z0.y, 0.f);
    }
}

// ------------------------- inverse: HC = aggT + irfft(aggF) ------------------
__global__ __launch_bounds__(256)
void inv_rfft_kernel(const float* __restrict__ AGG, float* __restrict__ HC,
                     const float2* __restrict__ tw, const float2* __restrict__ wi) {
    __shared__ float2 buf[4][2][128];
    __shared__ float2 sA[4][132];
    int g = threadIdx.x >> 6, t = threadIdx.x & 63;
    int row = (blockIdx.x << 2) + g;
    const float* aggr = AGG + (size_t)row * AGGW;
    const float2* A = reinterpret_cast<const float2*>(aggr + DIM);
    sA[g][t] = A[t];
    sA[g][t + 64] = A[t + 64];
    if (t == 0) sA[g][128] = A[128];
    __syncthreads();
#pragma unroll
    for (int u = 0; u < 2; u++) {
        int k = t + 64 * u;
        float2 Ak = sA[g][k], Am = sA[g][128 - k];
        float2 Ze = make_float2(0.5f * (Ak.x + Am.x), 0.5f * (Ak.y - Am.y));
        float2 hd = make_float2(0.5f * (Ak.x - Am.x), 0.5f * (Ak.y + Am.y));
        float2 Zo = cmulf(wi[k], hd);
        buf[g][0][k] = make_float2(Ze.x - Zo.y, Ze.y + Zo.x);
    }
    __syncthreads();
    fft128(buf[g][0], buf[g][1], t, +1.f, tw);
    float2* z = buf[g][1];
    float4 base = reinterpret_cast<const float4*>(aggr)[t];
    float2 z0 = z[2 * t], z1 = z[2 * t + 1];
    const float inv = 1.f / 128.f;
    float4 o = make_float4(base.x + z0.x * inv, base.y + z0.y * inv,
                           base.z + z1.x * inv, base.w + z1.y * inv);
    reinterpret_cast<float4*>(HC + (size_t)row * DIM)[t] = o;
}

// ------------------------- segmented aggregation (sorted edges) --------------
__device__ __forceinline__ float4 comb4(float4 a, float4 b, float w0, float w1) {
    return make_float4(w0 * a.x * b.x + w1 * (a.x + b.x),
                       w0 * a.y * b.y + w1 * (a.y + b.y),
                       w0 * a.z * b.z + w1 * (a.z + b.z),
                       w0 * a.w * b.w + w1 * (a.w + b.w));
}
__device__ __forceinline__ float4 spec4(float4 a, float4 b) {
    return make_float4(a.x * b.x + a.y * b.y,
                       a.y * b.x - a.x * b.y,
                       a.z * b.z + a.w * b.w,
                       a.w * b.z - a.z * b.w);
}
__device__ __forceinline__ float4 add4(float4 a, float4 b) {
    return make_float4(a.x + b.x, a.y + b.y, a.z + b.z, a.w + b.w);
}

__global__ __launch_bounds__(256)
void agg_kernel(const int2* __restrict__ edges, const int* __restrict__ off,
                const float* __restrict__ h,  const float* __restrict__ HS,
                const float* __restrict__ rel, const float* __restrict__ RS,
                const float* __restrict__ w, int wofs,
                float* __restrict__ AGG) {
    int v = (blockIdx.x * blockDim.x + threadIdx.x) >> 5;
    if (v >= N_NODES) return;
    int lane = threadIdx.x & 31;
    float w0 = w[wofs + 0], w1 = w[wofs + 1], w2 = w[wofs + 2];

    const float4* h4   = reinterpret_cast<const float4*>(h);
    const float4* rel4 = reinterpret_cast<const float4*>(rel);

    // self-loop (rel type 0)
    float4 T0 = comb4(h4[(size_t)v * 64 + lane],      rel4[lane],      w0, w1);
    float4 T1 = comb4(h4[(size_t)v * 64 + lane + 32], rel4[lane + 32], w0, w1);
    const float4* Hs0 = reinterpret_cast<const float4*>(HS + (size_t)v * SPEC_PAD);
    const float4* Rs0 = reinterpret_cast<const float4*>(RS);
    float4 F0 = spec4(Hs0[lane], Rs0[lane]);
    float4 F1 = spec4(Hs0[lane + 32], Rs0[lane + 32]);
    float2 Ft = make_float2(0.f, 0.f);
    if (lane == 0) {
        float2 a = *reinterpret_cast<const float2*>(HS + (size_t)v * SPEC_PAD + 256);
        float2 b = *reinterpret_cast<const float2*>(RS + 256);
        Ft = make_float2(a.x * b.x + a.y * b.y, a.y * b.x - a.x * b.y);
    }

    int e0 = off[v], e1 = off[v + 1];
    for (int e = e0; e < e1; e++) {
        int2 ed = edges[e];
        const float4* hs = reinterpret_cast<const float4*>(h + (size_t)ed.x * DIM);
        const float4* rt = reinterpret_cast<const float4*>(rel + (size_t)ed.y * DIM);
        T0 = add4(T0, comb4(hs[lane], rt[lane], w0, w1));
        T1 = add4(T1, comb4(hs[lane + 32], rt[lane + 32], w0, w1));
        const float4* Hse = reinterpret_cast<const float4*>(HS + (size_t)ed.x * SPEC_PAD);
        const float4* Rse = reinterpret_cast<const float4*>(RS + (size_t)ed.y * SPEC_PAD);
        F0 = add4(F0, spec4(Hse[lane], Rse[lane]));
        F1 = add4(F1, spec4(Hse[lane + 32], Rse[lane + 32]));
        if (lane == 0) {
            float2 a = *reinterpret_cast<const float2*>(HS + (size_t)ed.x * SPEC_PAD + 256);
            float2 b = *reinterpret_cast<const float2*>(RS + (size_t)ed.y * SPEC_PAD + 256);
            Ft.x += a.x * b.x + a.y * b.y;
            Ft.y += a.y * b.x - a.x * b.y;
        }
    }

    float* aggT = AGG + (size_t)v * AGGW;
    reinterpret_cast<float4*>(aggT)[lane]      = T0;
    reinterpret_cast<float4*>(aggT)[lane + 32] = T1;
    float* aggF = aggT + DIM;
    F0.x *= w2; F0.y *= w2; F0.z *= w2; F0.w *= w2;
    F1.x *= w2; F1.y *= w2; F1.z *= w2; F1.w *= w2;
    reinterpret_cast<float4*>(aggF)[lane]      = F0;
    reinterpret_cast<float4*>(aggF)[lane + 32] = F1;
    if (lane == 0)
        *reinterpret_cast<float2*>(aggF + 256) = make_float2(w2 * Ft.x, w2 * Ft.y);
}

// ------------------------- residual + LayerNorm + ReLU -----------------------
__global__ void epilogue_kernel(const float* __restrict__ OUT,
                                const float* __restrict__ h_in,
                                const float* __restrict__ bn,
                                const float* __restrict__ gamma,
                                const float* __restrict__ beta,
                                float* __restrict__ h_out) {
    int v = (blockIdx.x * blockDim.x + threadIdx.x) >> 5;
    if (v >= N_NODES) return;
    int lane = threadIdx.x & 31;
    const float* o  = OUT  + (size_t)v * DIM;
    const float* hi = h_in + (size_t)v * DIM;
    float z[8];
    float s = 0.f;
#pragma unroll
    for (int i = 0; i < 8; i++) {
        int d = lane + 32 * i;
        z[i] = o[d] + bn[d] + hi[d];
        s += z[i];
    }
#pragma unroll
    for (int off = 16; off; off >>= 1) s += __shfl_xor_sync(0xffffffffu, s, off);
    float mu = s * (1.f / DIM);
    float vv = 0.f;
#pragma unroll
    for (int i = 0; i < 8; i++) { float t = z[i] - mu; vv += t * t; }
#pragma unroll
    for (int off = 16; off; off >>= 1) vv += __shfl_xor_sync(0xffffffffu, vv, off);
    float rstd = rsqrtf(vv * (1.f / DIM) + LN_EPS);
    float* ho = h_out + (size_t)v * DIM;
#pragma unroll
    for (int i = 0; i < 8; i++) {
        int d = lane + 32 * i;
        float y = (z[i] - mu) * rstd * gamma[d] + beta[d];
        ho[d] = fmaxf(y, 0.f);
    }
}

// ------------------------- bf16x3 tensor-core GEMM ---------------------------
// C[m,n] = sum_k A[m,k] * B[n,k] (+ bias[n]).  A:[M,K] rm, B:[N,K] rm.
// Split x = hi + lo (bf16 each); C = Ah*Bh + Ah*Bl + Al*Bh (error ~2^-16).
#define GBK 32
#define GPAD 2

__device__ __forceinline__ void mma_bf16(float* d,
    uint32_t a0, uint32_t a1, uint32_t a2, uint32_t a3,
    uint32_t b0, uint32_t b1) {
    asm volatile(
        "mma.sync.aligned.m16n8k16.row.col.f32.bf16.bf16.f32 "
        "{%0,%1,%2,%3}, {%4,%5,%6,%7}, {%8,%9}, {%0,%1,%2,%3};"
        : "+f"(d[0]), "+f"(d[1]), "+f"(d[2]), "+f"(d[3])
        : "r"(a0), "r"(a1), "r"(a2), "r"(a3), "r"(b0), "r"(b1));
}

template<bool BIAS>
__global__ __launch_bounds__(256)
void bf16x3_gemm(const float* __restrict__ A, const float* __restrict__ B,
                 float* __restrict__ C, const float* __restrict__ bias,
                 int M, int N, int K) {
    __shared__ __align__(16) __nv_bfloat16 Ah[128][GBK + GPAD];
    __shared__ __align__(16) __nv_bfloat16 Al[128][GBK + GPAD];
    __shared__ __align__(16) __nv_bfloat16 Bh[128][GBK + GPAD];
    __shared__ __align__(16) __nv_bfloat16 Bl[128][GBK + GPAD];

    int tid = threadIdx.x;
    int lane = tid & 31, wid = tid >> 5;
    int wm = wid & 1, wn = wid >> 1;          // 2 x 4 warp grid
    int r = lane >> 2, cq = lane & 3;
    int bm = blockIdx.y * 128, bn = blockIdx.x * 128;

    float acc[4][4][4];
#pragma unroll
    for (int a = 0; a < 4; a++)
#pragma unroll
        for (int b = 0; b < 4; b++)
#pragma unroll
            for (int c = 0; c < 4; c++) acc[a][b][c] = 0.f;

    for (int k0 = 0; k0 < K; k0 += GBK) {
#pragma unroll
        for (int i = 0; i < 4; i++) {
            int idx = tid + 256 * i;              // 0..1023 float4 slots
            int row = idx >> 3, kc = (idx & 7) << 2;
            // A
            float4 av = make_float4(0.f, 0.f, 0.f, 0.f);
            if (bm + row < M)
                av = *reinterpret_cast<const float4*>(A + (size_t)(bm + row) * K + k0 + kc);
            float fx[4] = {av.x, av.y, av.z, av.w};
#pragma unroll
            for (int j = 0; j < 4; j++) {
                __nv_bfloat16 hi = __float2bfloat16(fx[j]);
                Ah[row][kc + j] = hi;
                Al[row][kc + j] = __float2bfloat16(fx[j] - __bfloat162float(hi));
            }
            // B
            float4 bv = make_float4(0.f, 0.f, 0.f, 0.f);
            if (bn + row < N)
                bv = *reinterpret_cast<const float4*>(B + (size_t)(bn + row) * K + k0 + kc);
            float gx[4] = {bv.x, bv.y, bv.z, bv.w};
#pragma unroll
            for (int j = 0; j < 4; j++) {
                __nv_bfloat16 hi = __float2bfloat16(gx[j]);
                Bh[row][kc + j] = hi;
                Bl[row][kc + j] = __float2bfloat16(gx[j] - __bfloat162float(hi));
            }
        }
        __syncthreads();

#pragma unroll
        for (int ks = 0; ks < 2; ks++) {
            int kb = ks * 16 + cq * 2;
            uint32_t bhf[4][2], blf[4][2];
#pragma unroll
            for (int nf = 0; nf < 4; nf++) {
                int col = wn * 32 + nf * 8 + r;
                bhf[nf][0] = *reinterpret_cast<const uint32_t*>(&Bh[col][kb]);
                bhf[nf][1] = *reinterpret_cast<const uint32_t*>(&Bh[col][kb + 8]);
                blf[nf][0] = *reinterpret_cast<const uint32_t*>(&Bl[col][kb]);
                blf[nf][1] = *reinterpret_cast<const uint32_t*>(&Bl[col][kb + 8]);
            }
#pragma unroll
            for (int mf = 0; mf < 4; mf++) {
                int row = wm * 64 + mf * 16 + r;
                uint32_t a0 = *reinterpret_cast<const uint32_t*>(&Ah[row][kb]);
                uint32_t a1 = *reinterpret_cast<const uint32_t*>(&Ah[row + 8][kb]);
                uint32_t a2 = *reinterpret_cast<const uint32_t*>(&Ah[row][kb + 8]);
                uint32_t a3 = *reinterpret_cast<const uint32_t*>(&Ah[row + 8][kb + 8]);
                uint32_t l0 = *reinterpret_cast<const uint32_t*>(&Al[row][kb]);
                uint32_t l1 = *reinterpret_cast<const uint32_t*>(&Al[row + 8][kb]);
                uint32_t l2 = *reinterpret_cast<const uint32_t*>(&Al[row][kb + 8]);
                uint32_t l3 = *reinterpret_cast<const uint32_t*>(&Al[row + 8][kb + 8]);
#pragma unroll
                for (int nf = 0; nf < 4; nf++) {
                    mma_bf16(acc[mf][nf], a0, a1, a2, a3, bhf[nf][0], bhf[nf][1]);
                    mma_bf16(acc[mf][nf], a0, a1, a2, a3, blf[nf][0], blf[nf][1]);
                    mma_bf16(acc[mf][nf], l0, l1, l2, l3, bhf[nf][0], bhf[nf][1]);
                }
            }
        }
        __syncthreads();
    }

    // epilogue: write C
#pragma unroll
    for (int mf = 0; mf < 4; mf++) {
        int row0 = bm + wm * 64 + mf * 16 + r;
#pragma unroll
        for (int nf = 0; nf < 4; nf++) {
            int col = bn + wn * 32 + nf * 8 + cq * 2;
            float bx = 0.f, by = 0.f;
            if (BIAS) { bx = bias[col]; by = bias[col + 1]; }
            if (row0 < M)
                *reinterpret_cast<float2*>(C + (size_t)row0 * N + col) =
                    make_float2(acc[mf][nf][0] + bx, acc[mf][nf][1] + by);
            if (row0 + 8 < M)
                *reinterpret_cast<float2*>(C + (size_t)(row0 + 8) * N + col) =
                    make_float2(acc[mf][nf][2] + bx, acc[mf][nf][3] + by);
        }
    }
}

// ------------------------- launch --------------------------------------------
extern "C" void kernel_launch(void* const* d_in, const int* in_sizes, int n_in,
                              void* d_out, int out_size) {
    (void)in_sizes; (void)n_in; (void)out_size;
    const int*   x    = (const int*)  d_in[0];
    const int*   eidx = (const int*)  d_in[1];
    const int*   et   = (const int*)  d_in[2];
    const float* emb  = (const float*)d_in[3];
    const float* rel1 = (const float*)d_in[4];
    const float* Wn1  = (const float*)d_in[7];
    const float* bn1  = (const float*)d_in[8];
    const float* cw1  = (const float*)d_in[9];
    const float* gm1  = (const float*)d_in[10];
    const float* bt1  = (const float*)d_in[11];
    const float* rel2 = (const float*)d_in[12];
    const float* Wr2  = (const float*)d_in[13];
    const float* br2  = (const float*)d_in[14];
    const float* Wn2  = (const float*)d_in[15];
    const float* bn2  = (const float*)d_in[16];
    const float* cw2  = (const float*)d_in[17];
    const float* gm2  = (const float*)d_in[18];
    const float* bt2  = (const float*)d_in[19];

    float* out_h    = (float*)d_out;
    float* out_rels = out_h + (size_t)N_NODES * DIM;
    const int* src = eidx;
    const int* dst = eidx + N_EDGES;

    float *pH, *pHS, *pRS, *pAGG, *pHC, *pOUT, *pTw, *pWt, *pWi, *pW;
    int *pDeg, *pOff, *pPos;
    int2* pEdges;
    cudaGetSymbolAddress((void**)&pH,    g_h);
    cudaGetSymbolAddress((void**)&pHS,   g_HS);
    cudaGetSymbolAddress((void**)&pRS,   g_RS);
    cudaGetSymbolAddress((void**)&pAGG,  g_AGG);
    cudaGetSymbolAddress((void**)&pHC,   g_HC);
    cudaGetSymbolAddress((void**)&pOUT,  g_OUT);
    cudaGetSymbolAddress((void**)&pTw,   g_tw);
    cudaGetSymbolAddress((void**)&pWt,   g_wt);
    cudaGetSymbolAddress((void**)&pWi,   g_wi);
    cudaGetSymbolAddress((void**)&pW,    g_w);
    cudaGetSymbolAddress((void**)&pDeg,  g_deg);
    cudaGetSymbolAddress((void**)&pOff,  g_off);
    cudaGetSymbolAddress((void**)&pPos,  g_pos);
    cudaGetSymbolAddress((void**)&pEdges, g_edges);

    const float2* tw = (const float2*)pTw;
    const float2* wt = (const float2*)pWt;
    const float2* wi = (const float2*)pWi;

    build_tw_kernel<<<2, 256>>>(pTw, pWt, pWi);
    softmax_kernel<<<1, 32>>>(cw1, cw2, pW);
    gather_kernel<<<(N_NODES * (DIM / 4) + 255) / 256, 256>>>(x, emb, pH);

    // edge sort by dst (once; shared by both layers)
    zero_deg_kernel<<<(N_NODES + 255) / 256, 256>>>(pDeg);
    hist_kernel<<<(N_EDGES + 255) / 256, 256>>>(dst, pDeg);
    scan_kernel<<<1, 1024>>>(pDeg, pOff, pPos);
    scatter_kernel<<<(N_EDGES + 255) / 256, 256>>>(src, dst, et, pPos, pEdges);

    const int warps_nodes = (N_NODES * 32 + 255) / 256;

    for (int L = 0; L < 2; L++) {
        const float* rel = (L == 0) ? rel1 : rel2;
        const float* Wn  = (L == 0) ? Wn1  : Wn2;
        const float* bn  = (L == 0) ? bn1  : bn2;
        const float* gm  = (L == 0) ? gm1  : gm2;
        const float* bt  = (L == 0) ? bt1  : bt2;
        float* hout      = (L == 0) ? pH   : out_h;

        fwd_rfft_kernel<<<N_NODES / 4, 256>>>(pH, pHS, tw, wt);
        fwd_rfft_kernel<<<NRELS / 4, 256>>>(rel, pRS, tw, wt);
        agg_kernel<<<warps_nodes, 256>>>(pEdges, pOff, pH, pHS, rel, pRS, pW, 3 * L, pAGG);
        inv_rfft_kernel<<<N_NODES / 4, 256>>>(pAGG, pHC, tw, wi);
        bf16x3_gemm<false><<<dim3(2, (N_NODES + 127) / 128), 256>>>(
            pHC, Wn, pOUT, nullptr, N_NODES, DIM, DIM);
        epilogue_kernel<<<warps_nodes, 256>>>(pOUT, pH, bn, gm, bt, hout);
    }

    bf16x3_gemm<true><<<dim3(2, (NRELS + 127) / 128), 256>>>(
        rel2, Wr2, out_rels, br2, NRELS, DIM, DIM);
}

// round 4
// speedup vs baseline: 2.5670x; 1.0852x over previous
#include <cuda_runtime.h>
#include <cuda_bf16.h>
#include <math.h>
#include <stdint.h>

#define N_NODES 50000
#define N_EDGES 250000
#define DIM     256
#define NRELS   400
#define SPEC_PAD 260     // 258 floats (129 complex bins) + 2 pad
#define LN_EPS  1e-5f

// ------------------------- scratch (device globals) --------------------------
__device__ float g_h  [(size_t)N_NODES * DIM];
__device__ float g_HS [(size_t)N_NODES * SPEC_PAD];
__device__ float g_RS [(size_t)NRELS   * SPEC_PAD];
__device__ float g_HC [(size_t)N_NODES * DIM];
__device__ float g_OUT[(size_t)N_NODES * DIM];
__device__ float g_tw [7 * 64 * 2];
__device__ float g_wt [129 * 2];
__device__ float g_wi [129 * 2];
__device__ float g_w  [6];
__device__ int   g_deg[N_NODES];
__device__ int   g_off[N_NODES + 1];
__device__ int   g_pos[N_NODES];
__device__ int2  g_edges[N_EDGES];     // (src, et) sorted by dst

// ------------------------- small helpers -------------------------------------
__device__ __forceinline__ float2 cmulf(float2 a, float2 b) {
    return make_float2(a.x * b.x - a.y * b.y, a.x * b.y + a.y * b.x);
}
__device__ __forceinline__ float4 comb4(float4 a, float4 b, float w0, float w1) {
    return make_float4(w0 * a.x * b.x + w1 * (a.x + b.x),
                       w0 * a.y * b.y + w1 * (a.y + b.y),
                       w0 * a.z * b.z + w1 * (a.z + b.z),
                       w0 * a.w * b.w + w1 * (a.w + b.w));
}
__device__ __forceinline__ float4 spec4(float4 a, float4 b) {
    return make_float4(a.x * b.x + a.y * b.y,
                       a.y * b.x - a.x * b.y,
                       a.z * b.z + a.w * b.w,
                       a.w * b.z - a.z * b.w);
}
__device__ __forceinline__ float4 add4(float4 a, float4 b) {
    return make_float4(a.x + b.x, a.y + b.y, a.z + b.z, a.w + b.w);
}

// ------------------------- table builders ------------------------------------
__global__ void build_tw_kernel(float* tw, float* wt, float* wi) {
    int i = blockIdx.x * blockDim.x + threadIdx.x;
    if (i < 7 * 64) {
        int s = i >> 6, j = i & 63;
        int l = 64 >> s;
        float2 v = make_float2(0.f, 0.f);
        if (j < l) {
            double a = (double)j / (double)l;
            v = make_float2((float)cospi(a), (float)sinpi(a));
        }
        reinterpret_cast<float2*>(tw)[i] = v;
    }
    if (i < 129) {
        double a = (double)i / 128.0;
        reinterpret_cast<float2*>(wt)[i] = make_float2((float)cospi(a), (float)(-sinpi(a)));
        reinterpret_cast<float2*>(wi)[i] = make_float2((float)cospi(a), (float)( sinpi(a)));
    }
}

__global__ void softmax_kernel(const float* __restrict__ cw1,
                               const float* __restrict__ cw2,
                               float* __restrict__ w) {
    if (threadIdx.x == 0 && blockIdx.x == 0) {
        for (int L = 0; L < 2; L++) {
            const float* c = (L == 0) ? cw1 : cw2;
            float m = fmaxf(c[0], fmaxf(c[1], c[2]));
            float e0 = expf(c[0] - m), e1 = expf(c[1] - m), e2 = expf(c[2] - m);
            float s = e0 + e1 + e2;
            w[L * 3 + 0] = e0 / s; w[L * 3 + 1] = e1 / s; w[L * 3 + 2] = e2 / s;
        }
    }
}

// ------------------------- edge sorting (counting sort by dst) ---------------
__global__ void zero_deg_kernel(int* deg) {
    int i = blockIdx.x * blockDim.x + threadIdx.x;
    if (i < N_NODES) deg[i] = 0;
}
__global__ void hist_kernel(const int* __restrict__ dst, int* deg) {
    int e = blockIdx.x * blockDim.x + threadIdx.x;
    if (e < N_EDGES) atomicAdd(&deg[dst[e]], 1);
}
__global__ __launch_bounds__(1024)
void scan_kernel(const int* __restrict__ deg, int* off, int* pos) {
    __shared__ int ps[1024];
    int t = threadIdx.x;
    const int CH = (N_NODES + 1023) / 1024;
    int b0 = t * CH, b1 = min(b0 + CH, N_NODES);
    int s = 0;
    for (int i = b0; i < b1; i++) s += deg[i];
    ps[t] = s;
    __syncthreads();
    for (int o = 1; o < 1024; o <<= 1) {
        int u = (t >= o) ? ps[t - o] : 0;
        __syncthreads();
        ps[t] += u;
        __syncthreads();
    }
    int run = ps[t] - s;
    for (int i = b0; i < b1; i++) {
        off[i] = run; pos[i] = run; run += deg[i];
    }
    if (t == 1023) off[N_NODES] = ps[1023];
}
__global__ void scatter_kernel(const int* __restrict__ src,
                               const int* __restrict__ dst,
                               const int* __restrict__ et,
                               int* pos, int2* edges) {
    int e = blockIdx.x * blockDim.x + threadIdx.x;
    if (e >= N_EDGES) return;
    int p = atomicAdd(&pos[dst[e]], 1);
    edges[p] = make_int2(src[e], et[e]);
}

// ------------------------- 128-pt Stockham FFT (64 threads/row) --------------
__device__ __forceinline__ void fft128(float2* b0, float2* b1, int t, float sgn,
                                       const float2* __restrict__ tw) {
    float2* src = b0;
    float2* dst = b1;
#pragma unroll
    for (int s = 0; s < 7; s++) {
        int m = 1 << s;
        int j = t >> s;
        float2 w = tw[(s << 6) + j];
        w.y *= sgn;
        float2 c0 = src[t];
        float2 c1 = src[t + 64];
        float2 sum = make_float2(c0.x + c1.x, c0.y + c1.y);
        float2 d   = make_float2(c0.x - c1.x, c0.y - c1.y);
        int idx = (t & (m - 1)) | ((t >> s) << (s + 1));
        dst[idx]     = sum;
        dst[idx + m] = cmulf(d, w);
        float2* tmp = src; src = dst; dst = tmp;
        __syncthreads();
    }
}

// forward untangle + store of a spectrum row; Z = fft of packed row, t=0..63
__device__ __forceinline__ void rfft_untangle_store(
    float2* Z, float* Srow, int t, const float2* __restrict__ wt) {
#pragma unroll
    for (int u = 0; u < 2; u++) {
        int k = t + 64 * u;
        float2 Zk = Z[k];
        float2 Zm = Z[(128 - k) & 127];
        float2 Ze = make_float2(0.5f * (Zk.x + Zm.x), 0.5f * (Zk.y - Zm.y));
        float2 d  = make_float2(Zk.x - Zm.x, Zk.y + Zm.y);
        float2 Zo = make_float2(0.5f * d.y, -0.5f * d.x);
        float2 W  = wt[k];
        float2 H  = make_float2(Ze.x + W.x * Zo.x - W.y * Zo.y,
                                Ze.y + W.x * Zo.y + W.y * Zo.x);
        *reinterpret_cast<float2*>(Srow + 2 * k) = H;
    }
    if (t == 0) {
        float2 Z0 = Z[0];
        *reinterpret_cast<float2*>(Srow + 256) = make_float2(Z0.x - Z0.y, 0.f);
    }
}

// ------------------------- gather + forward rfft (fused) ---------------------
__global__ __launch_bounds__(256)
void gather_fft_kernel(const int* __restrict__ x, const float* __restrict__ emb,
                       float* __restrict__ h, float* __restrict__ S,
                       const float2* __restrict__ tw, const float2* __restrict__ wt) {
    __shared__ float2 buf[4][2][128];
    int g = threadIdx.x >> 6, t = threadIdx.x & 63;
    int row = (blockIdx.x << 2) + g;
    float4 v = reinterpret_cast<const float4*>(emb + (size_t)x[row] * DIM)[t];
    reinterpret_cast<float4*>(h + (size_t)row * DIM)[t] = v;
    buf[g][0][2 * t]     = make_float2(v.x, v.y);
    buf[g][0][2 * t + 1] = make_float2(v.z, v.w);
    __syncthreads();
    fft128(buf[g][0], buf[g][1], t, -1.f, tw);
    rfft_untangle_store(buf[g][1], S + (size_t)row * SPEC_PAD, t, wt);
}

// ------------------------- plain forward rfft (rel tables) -------------------
__global__ __launch_bounds__(256)
void fwd_rfft_kernel(const float* __restrict__ X, float* __restrict__ S,
                     const float2* __restrict__ tw, const float2* __restrict__ wt) {
    __shared__ float2 buf[4][2][128];
    int g = threadIdx.x >> 6, t = threadIdx.x & 63;
    int row = (blockIdx.x << 2) + g;
    float4 v = reinterpret_cast<const float4*>(X + (size_t)row * DIM)[t];
    buf[g][0][2 * t]     = make_float2(v.x, v.y);
    buf[g][0][2 * t + 1] = make_float2(v.z, v.w);
    __syncthreads();
    fft128(buf[g][0], buf[g][1], t, -1.f, tw);
    rfft_untangle_store(buf[g][1], S + (size_t)row * SPEC_PAD, t, wt);
}

// --------------- aggregation + inverse rfft (fused) --------------------------
// 64 threads per node (2 warps). Thread t accumulates:
//   T = time cols [4t..4t+3],  F = spectral bins (2t, 2t+1) as 2x complex.
// Then group-local inverse rFFT; writes HC = aggT + irfft(aggF) directly.
__global__ __launch_bounds__(256)
void agg_inv_kernel(const int2* __restrict__ edges, const int* __restrict__ off,
                    const float* __restrict__ h,  const float* __restrict__ HS,
                    const float* __restrict__ rel, const float* __restrict__ RS,
                    const float* __restrict__ w, int wofs,
                    float* __restrict__ HC,
                    const float2* __restrict__ tw, const float2* __restrict__ wi) {
    __shared__ float2 buf[4][2][128];
    __shared__ float2 sA[4][132];
    int g = threadIdx.x >> 6, t = threadIdx.x & 63;
    int v = (blockIdx.x << 2) + g;
    float w0 = w[wofs + 0], w1 = w[wofs + 1], w2 = w[wofs + 2];

    const float4* h4   = reinterpret_cast<const float4*>(h);
    const float4* rel4 = reinterpret_cast<const float4*>(rel);

    // self-loop (rel type 0)
    float4 T = comb4(h4[(size_t)v * 64 + t], rel4[t], w0, w1);
    float4 F = spec4(reinterpret_cast<const float4*>(HS + (size_t)v * SPEC_PAD)[t],
                     reinterpret_cast<const float4*>(RS)[t]);
    float2 Ft = make_float2(0.f, 0.f);
    if (t == 0) {
        float2 a = *reinterpret_cast<const float2*>(HS + (size_t)v * SPEC_PAD + 256);
        float2 b = *reinterpret_cast<const float2*>(RS + 256);
        Ft = make_float2(a.x * b.x + a.y * b.y, a.y * b.x - a.x * b.y);
    }

    int e0 = off[v], e1 = off[v + 1];
    for (int e = e0; e < e1; e++) {
        int2 ed = edges[e];
        T = add4(T, comb4(h4[(size_t)ed.x * 64 + t],
                          rel4[(size_t)ed.y * 64 + t], w0, w1));
        F = add4(F, spec4(reinterpret_cast<const float4*>(HS + (size_t)ed.x * SPEC_PAD)[t],
                          reinterpret_cast<const float4*>(RS + (size_t)ed.y * SPEC_PAD)[t]));
        if (t == 0) {
            float2 a = *reinterpret_cast<const float2*>(HS + (size_t)ed.x * SPEC_PAD + 256);
            float2 b = *reinterpret_cast<const float2*>(RS + (size_t)ed.y * SPEC_PAD + 256);
            Ft.x += a.x * b.x + a.y * b.y;
            Ft.y += a.y * b.x - a.x * b.y;
        }
    }

    // stage spectrum (scaled by w2) into shared
    sA[g][2 * t]     = make_float2(w2 * F.x, w2 * F.y);
    sA[g][2 * t + 1] = make_float2(w2 * F.z, w2 * F.w);
    if (t == 0) sA[g][128] = make_float2(w2 * Ft.x, w2 * Ft.y);
    __syncthreads();

    // inverse untangle -> packed complex
#pragma unroll
    for (int u = 0; u < 2; u++) {
        int k = t + 64 * u;
        float2 Ak = sA[g][k], Am = sA[g][128 - k];
        float2 Ze = make_float2(0.5f * (Ak.x + Am.x), 0.5f * (Ak.y - Am.y));
        float2 hd = make_float2(0.5f * (Ak.x - Am.x), 0.5f * (Ak.y + Am.y));
        float2 Zo = cmulf(wi[k], hd);
        buf[g][0][k] = make_float2(Ze.x - Zo.y, Ze.y + Zo.x);
    }
    __syncthreads();
    fft128(buf[g][0], buf[g][1], t, +1.f, tw);
    float2 z0 = buf[g][1][2 * t], z1 = buf[g][1][2 * t + 1];
    const float inv = 1.f / 128.f;
    float4 o = make_float4(T.x + z0.x * inv, T.y + z0.y * inv,
                           T.z + z1.x * inv, T.w + z1.y * inv);
    reinterpret_cast<float4*>(HC + (size_t)v * DIM)[t] = o;
}

// --------- residual + LN + ReLU, optionally fused with forward rfft ----------
template<bool DO_FFT>
__global__ __launch_bounds__(256)
void epilogue_fft_kernel(const float* __restrict__ OUT,
                         const float* __restrict__ h_in,
                         const float* __restrict__ bn,
                         const float* __restrict__ gamma,
                         const float* __restrict__ beta,
                         float* __restrict__ h_out,
                         float* __restrict__ S,
                         const float2* __restrict__ tw,
                         const float2* __restrict__ wt) {
    __shared__ float2 buf[4][2][128];
    __shared__ float sred[4][2];
    int g = threadIdx.x >> 6, t = threadIdx.x & 63;
    int wsub = t >> 5;                    // warp within group
    int v = (blockIdx.x << 2) + g;

    float4 o  = reinterpret_cast<const float4*>(OUT  + (size_t)v * DIM)[t];
    float4 hi = reinterpret_cast<const float4*>(h_in + (size_t)v * DIM)[t];
    float4 bb = reinterpret_cast<const float4*>(bn)[t];
    float4 z = make_float4(o.x + bb.x + hi.x, o.y + bb.y + hi.y,
                           o.z + bb.z + hi.z, o.w + bb.w + hi.w);
    float s = z.x + z.y + z.z + z.w;
#pragma unroll
    for (int ofs = 16; ofs; ofs >>= 1) s += __shfl_xor_sync(0xffffffffu, s, ofs);
    if ((t & 31) == 0) sred[g][wsub] = s;
    __syncthreads();
    float mu = (sred[g][0] + sred[g][1]) * (1.f / DIM);
    __syncthreads();
    float4 zc = make_float4(z.x - mu, z.y - mu, z.z - mu, z.w - mu);
    float vv = zc.x * zc.x + zc.y * zc.y + zc.z * zc.z + zc.w * zc.w;
#pragma unroll
    for (int ofs = 16; ofs; ofs >>= 1) vv += __shfl_xor_sync(0xffffffffu, vv, ofs);
    if ((t & 31) == 0) sred[g][wsub] = vv;
    __syncthreads();
    float rstd = rsqrtf((sred[g][0] + sred[g][1]) * (1.f / DIM) + LN_EPS);
    float4 gm = reinterpret_cast<const float4*>(gamma)[t];
    float4 bt = reinterpret_cast<const float4*>(beta)[t];
    float4 y = make_float4(fmaxf(zc.x * rstd * gm.x + bt.x, 0.f),
                           fmaxf(zc.y * rstd * gm.y + bt.y, 0.f),
                           fmaxf(zc.z * rstd * gm.z + bt.z, 0.f),
                           fmaxf(zc.w * rstd * gm.w + bt.w, 0.f));
    reinterpret_cast<float4*>(h_out + (size_t)v * DIM)[t] = y;
    if (DO_FFT) {
        buf[g][0][2 * t]     = make_float2(y.x, y.y);
        buf[g][0][2 * t + 1] = make_float2(y.z, y.w);
        __syncthreads();
        fft128(buf[g][0], buf[g][1], t, -1.f, tw);
        rfft_untangle_store(buf[g][1], S + (size_t)v * SPEC_PAD, t, wt);
    }
}

// ------------------------- bf16x3 tensor-core GEMM ---------------------------
#define GBK 32
#define GPAD 2

__device__ __forceinline__ void mma_bf16(float* d,
    uint32_t a0, uint32_t a1, uint32_t a2, uint32_t a3,
    uint32_t b0, uint32_t b1) {
    asm volatile(
        "mma.sync.aligned.m16n8k16.row.col.f32.bf16.bf16.f32 "
        "{%0,%1,%2,%3}, {%4,%5,%6,%7}, {%8,%9}, {%0,%1,%2,%3};"
        : "+f"(d[0]), "+f"(d[1]), "+f"(d[2]), "+f"(d[3])
        : "r"(a0), "r"(a1), "r"(a2), "r"(a3), "r"(b0), "r"(b1));
}

template<bool BIAS>
__global__ __launch_bounds__(256)
void bf16x3_gemm(const float* __restrict__ A, const float* __restrict__ B,
                 float* __restrict__ C, const float* __restrict__ bias,
                 int M, int N, int K) {
    __shared__ __align__(16) __nv_bfloat16 Ah[128][GBK + GPAD];
    __shared__ __align__(16) __nv_bfloat16 Al[128][GBK + GPAD];
    __shared__ __align__(16) __nv_bfloat16 Bh[128][GBK + GPAD];
    __shared__ __align__(16) __nv_bfloat16 Bl[128][GBK + GPAD];

    int tid = threadIdx.x;
    int lane = tid & 31, wid = tid >> 5;
    int wm = wid & 1, wn = wid >> 1;
    int r = lane >> 2, cq = lane & 3;
    int bm = blockIdx.y * 128, bn = blockIdx.x * 128;

    float acc[4][4][4];
#pragma unroll
    for (int a = 0; a < 4; a++)
#pragma unroll
        for (int b = 0; b < 4; b++)
#pragma unroll
            for (int c = 0; c < 4; c++) acc[a][b][c] = 0.f;

    for (int k0 = 0; k0 < K; k0 += GBK) {
#pragma unroll
        for (int i = 0; i < 4; i++) {
            int idx = tid + 256 * i;
            int row = idx >> 3, kc = (idx & 7) << 2;
            float4 av = make_float4(0.f, 0.f, 0.f, 0.f);
            if (bm + row < M)
                av = *reinterpret_cast<const float4*>(A + (size_t)(bm + row) * K + k0 + kc);
            float fx[4] = {av.x, av.y, av.z, av.w};
#pragma unroll
            for (int j = 0; j < 4; j++) {
                __nv_bfloat16 hi = __float2bfloat16(fx[j]);
                Ah[row][kc + j] = hi;
                Al[row][kc + j] = __float2bfloat16(fx[j] - __bfloat162float(hi));
            }
            float4 bv = make_float4(0.f, 0.f, 0.f, 0.f);
            if (bn + row < N)
                bv = *reinterpret_cast<const float4*>(B + (size_t)(bn + row) * K + k0 + kc);
            float gx[4] = {bv.x, bv.y, bv.z, bv.w};
#pragma unroll
            for (int j = 0; j < 4; j++) {
                __nv_bfloat16 hi = __float2bfloat16(gx[j]);
                Bh[row][kc + j] = hi;
                Bl[row][kc + j] = __float2bfloat16(gx[j] - __bfloat162float(hi));
            }
        }
        __syncthreads();

#pragma unroll
        for (int ks = 0; ks < 2; ks++) {
            int kb = ks * 16 + cq * 2;
            uint32_t bhf[4][2], blf[4][2];
#pragma unroll
            for (int nf = 0; nf < 4; nf++) {
                int col = wn * 32 + nf * 8 + r;
                bhf[nf][0] = *reinterpret_cast<const uint32_t*>(&Bh[col][kb]);
                bhf[nf][1] = *reinterpret_cast<const uint32_t*>(&Bh[col][kb + 8]);
                blf[nf][0] = *reinterpret_cast<const uint32_t*>(&Bl[col][kb]);
                blf[nf][1] = *reinterpret_cast<const uint32_t*>(&Bl[col][kb + 8]);
            }
#pragma unroll
            for (int mf = 0; mf < 4; mf++) {
                int row = wm * 64 + mf * 16 + r;
                uint32_t a0 = *reinterpret_cast<const uint32_t*>(&Ah[row][kb]);
                uint32_t a1 = *reinterpret_cast<const uint32_t*>(&Ah[row + 8][kb]);
                uint32_t a2 = *reinterpret_cast<const uint32_t*>(&Ah[row][kb + 8]);
                uint32_t a3 = *reinterpret_cast<const uint32_t*>(&Ah[row + 8][kb + 8]);
                uint32_t l0 = *reinterpret_cast<const uint32_t*>(&Al[row][kb]);
                uint32_t l1 = *reinterpret_cast<const uint32_t*>(&Al[row + 8][kb]);
                uint32_t l2 = *reinterpret_cast<const uint32_t*>(&Al[row][kb + 8]);
                uint32_t l3 = *reinterpret_cast<const uint32_t*>(&Al[row + 8][kb + 8]);
#pragma unroll
                for (int nf = 0; nf < 4; nf++) {
                    mma_bf16(acc[mf][nf], a0, a1, a2, a3, bhf[nf][0], bhf[nf][1]);
                    mma_bf16(acc[mf][nf], a0, a1, a2, a3, blf[nf][0], blf[nf][1]);
                    mma_bf16(acc[mf][nf], l0, l1, l2, l3, bhf[nf][0], bhf[nf][1]);
                }
            }
        }
        __syncthreads();
    }

#pragma unroll
    for (int mf = 0; mf < 4; mf++) {
        int row0 = bm + wm * 64 + mf * 16 + r;
#pragma unroll
        for (int nf = 0; nf < 4; nf++) {
            int col = bn + wn * 32 + nf * 8 + cq * 2;
            float bx = 0.f, by = 0.f;
            if (BIAS) { bx = bias[col]; by = bias[col + 1]; }
            if (row0 < M)
                *reinterpret_cast<float2*>(C + (size_t)row0 * N + col) =
                    make_float2(acc[mf][nf][0] + bx, acc[mf][nf][1] + by);
            if (row0 + 8 < M)
                *reinterpret_cast<float2*>(C + (size_t)(row0 + 8) * N + col) =
                    make_float2(acc[mf][nf][2] + bx, acc[mf][nf][3] + by);
        }
    }
}

// ------------------------- launch --------------------------------------------
extern "C" void kernel_launch(void* const* d_in, const int* in_sizes, int n_in,
                              void* d_out, int out_size) {
    (void)in_sizes; (void)n_in; (void)out_size;
    const int*   x    = (const int*)  d_in[0];
    const int*   eidx = (const int*)  d_in[1];
    const int*   et   = (const int*)  d_in[2];
    const float* emb  = (const float*)d_in[3];
    const float* rel1 = (const float*)d_in[4];
    const float* Wn1  = (const float*)d_in[7];
    const float* bn1  = (const float*)d_in[8];
    const float* cw1  = (const float*)d_in[9];
    const float* gm1  = (const float*)d_in[10];
    const float* bt1  = (const float*)d_in[11];
    const float* rel2 = (const float*)d_in[12];
    const float* Wr2  = (const float*)d_in[13];
    const float* br2  = (const float*)d_in[14];
    const float* Wn2  = (const float*)d_in[15];
    const float* bn2  = (const float*)d_in[16];
    const float* cw2  = (const float*)d_in[17];
    const float* gm2  = (const float*)d_in[18];
    const float* bt2  = (const float*)d_in[19];

    float* out_h    = (float*)d_out;
    float* out_rels = out_h + (size_t)N_NODES * DIM;
    const int* src = eidx;
    const int* dst = eidx + N_EDGES;

    float *pH, *pHS, *pRS, *pHC, *pOUT, *pTw, *pWt, *pWi, *pW;
    int *pDeg, *pOff, *pPos;
    int2* pEdges;
    cudaGetSymbolAddress((void**)&pH,    g_h);
    cudaGetSymbolAddress((void**)&pHS,   g_HS);
    cudaGetSymbolAddress((void**)&pRS,   g_RS);
    cudaGetSymbolAddress((void**)&pHC,   g_HC);
    cudaGetSymbolAddress((void**)&pOUT,  g_OUT);
    cudaGetSymbolAddress((void**)&pTw,   g_tw);
    cudaGetSymbolAddress((void**)&pWt,   g_wt);
    cudaGetSymbolAddress((void**)&pWi,   g_wi);
    cudaGetSymbolAddress((void**)&pW,    g_w);
    cudaGetSymbolAddress((void**)&pDeg,  g_deg);
    cudaGetSymbolAddress((void**)&pOff,  g_off);
    cudaGetSymbolAddress((void**)&pPos,  g_pos);
    cudaGetSymbolAddress((void**)&pEdges, g_edges);

    const float2* tw = (const float2*)pTw;
    const float2* wt = (const float2*)pWt;
    const float2* wi = (const float2*)pWi;

    build_tw_kernel<<<2, 256>>>(pTw, pWt, pWi);
    softmax_kernel<<<1, 32>>>(cw1, cw2, pW);

    // edge sort by dst (once; shared by both layers)
    zero_deg_kernel<<<(N_NODES + 255) / 256, 256>>>(pDeg);
    hist_kernel<<<(N_EDGES + 255) / 256, 256>>>(dst, pDeg);
    scan_kernel<<<1, 1024>>>(pDeg, pOff, pPos);
    scatter_kernel<<<(N_EDGES + 255) / 256, 256>>>(src, dst, et, pPos, pEdges);

    // h = emb[x]; HS = rfft(h)  (fused)
    gather_fft_kernel<<<N_NODES / 4, 256>>>(x, emb, pH, pHS, tw, wt);

    for (int L = 0; L < 2; L++) {
        const float* rel = (L == 0) ? rel1 : rel2;
        const float* Wn  = (L == 0) ? Wn1  : Wn2;
        const float* bn  = (L == 0) ? bn1  : bn2;
        const float* gm  = (L == 0) ? gm1  : gm2;
        const float* bt  = (L == 0) ? bt1  : bt2;

        fwd_rfft_kernel<<<NRELS / 4, 256>>>(rel, pRS, tw, wt);
        agg_inv_kernel<<<N_NODES / 4, 256>>>(pEdges, pOff, pH, pHS, rel, pRS,
                                             pW, 3 * L, pHC, tw, wi);
        bf16x3_gemm<false><<<dim3(2, (N_NODES + 127) / 128), 256>>>(
            pHC, Wn, pOUT, nullptr, N_NODES, DIM, DIM);
        if (L == 0) {
            // residual+LN+ReLU fused with next layer's forward rfft
            epilogue_fft_kernel<true><<<N_NODES / 4, 256>>>(
                pOUT, pH, bn, gm, bt, pH, pHS, tw, wt);
        } else {
            epilogue_fft_kernel<false><<<N_NODES / 4, 256>>>(
                pOUT, pH, bn, gm, bt, out_h, nullptr, tw, wt);
        }
    }

    bf16x3_gemm<true><<<dim3(2, (NRELS + 127) / 128), 256>>>(
        rel2, Wr2, out_rels, br2, NRELS, DIM, DIM);
}

// round 5
// speedup vs baseline: 2.8070x; 1.0935x over previous
#include <cuda_runtime.h>
#include <cuda_bf16.h>
#include <cuda_fp16.h>
#include <math.h>
#include <stdint.h>

#define N_NODES 50000
#define N_EDGES 250000
#define DIM     256
#define NRELS   400
#define HROW2   128     // h row: 128 half2 (256 vals) = 512 B
#define SROW2   130     // spec row: 129 complex bins as half2 + 1 pad = 520 B
#define LN_EPS  1e-5f

// ------------------------- scratch (device globals) --------------------------
__device__ float   g_h  [(size_t)N_NODES * DIM];     // fp32 h (residual path)
__device__ float   g_HC [(size_t)N_NODES * DIM];     // aggT + irfft(aggF)
__device__ float   g_Z  [(size_t)N_NODES * DIM];     // gemm out + bias + resid
__device__ __half2 g_hH [(size_t)N_NODES * HROW2];   // h as fp16
__device__ __half2 g_HSH[(size_t)N_NODES * SROW2];   // rfft(h) as fp16
__device__ __half2 g_rH [(size_t)NRELS   * HROW2];   // rel as fp16
__device__ __half2 g_RSH[(size_t)NRELS   * SROW2];   // rfft(rel) as fp16
__device__ float   g_tw [7 * 64 * 2];
__device__ float   g_wt [129 * 2];
__device__ float   g_wi [129 * 2];
__device__ float   g_w  [6];
__device__ int     g_deg[N_NODES];
__device__ int     g_off[N_NODES + 1];
__device__ int     g_pos[N_NODES];
__device__ int2    g_edges[N_EDGES];                 // (src, et) sorted by dst

// ------------------------- small helpers -------------------------------------
__device__ __forceinline__ float2 cmulf(float2 a, float2 b) {
    return make_float2(a.x * b.x - a.y * b.y, a.x * b.y + a.y * b.x);
}
__device__ __forceinline__ float4 comb4(float4 a, float4 b, float w0, float w1) {
    return make_float4(w0 * a.x * b.x + w1 * (a.x + b.x),
                       w0 * a.y * b.y + w1 * (a.y + b.y),
                       w0 * a.z * b.z + w1 * (a.z + b.z),
                       w0 * a.w * b.w + w1 * (a.w + b.w));
}
__device__ __forceinline__ float4 spec4(float4 a, float4 b) {
    return make_float4(a.x * b.x + a.y * b.y,
                       a.y * b.x - a.x * b.y,
                       a.z * b.z + a.w * b.w,
                       a.w * b.z - a.z * b.w);
}
__device__ __forceinline__ float4 add4(float4 a, float4 b) {
    return make_float4(a.x + b.x, a.y + b.y, a.z + b.z, a.w + b.w);
}
// load 4 consecutive halves (one 8B transaction) -> float4
__device__ __forceinline__ float4 ldh4(const __half2* row, int i) {
    uint2 raw = reinterpret_cast<const uint2*>(row)[i];
    float2 lo = __half22float2(*reinterpret_cast<__half2*>(&raw.x));
    float2 hi = __half22float2(*reinterpret_cast<__half2*>(&raw.y));
    return make_float4(lo.x, lo.y, hi.x, hi.y);
}

// ------------------------- fused setup kernel --------------------------------
__global__ void setup_kernel(float* tw, float* wt, float* wi,
                             const float* __restrict__ cw1,
                             const float* __restrict__ cw2, float* w,
                             int* deg) {
    int i = blockIdx.x * blockDim.x + threadIdx.x;
    if (i < 7 * 64) {
        int s = i >> 6, j = i & 63;
        int l = 64 >> s;
        float2 v = make_float2(0.f, 0.f);
        if (j < l) {
            double a = (double)j / (double)l;
            v = make_float2((float)cospi(a), (float)sinpi(a));
        }
        reinterpret_cast<float2*>(tw)[i] = v;
    }
    if (i < 129) {
        double a = (double)i / 128.0;
        reinterpret_cast<float2*>(wt)[i] = make_float2((float)cospi(a), (float)(-sinpi(a)));
        reinterpret_cast<float2*>(wi)[i] = make_float2((float)cospi(a), (float)( sinpi(a)));
    }
    if (i == 0) {
        for (int L = 0; L < 2; L++) {
            const float* c = (L == 0) ? cw1 : cw2;
            float m = fmaxf(c[0], fmaxf(c[1], c[2]));
            float e0 = expf(c[0] - m), e1 = expf(c[1] - m), e2 = expf(c[2] - m);
            float s = e0 + e1 + e2;
            w[L * 3 + 0] = e0 / s; w[L * 3 + 1] = e1 / s; w[L * 3 + 2] = e2 / s;
        }
    }
    if (i < N_NODES) deg[i] = 0;
}

// ------------------------- edge sorting (counting sort by dst) ---------------
__global__ void hist_kernel(const int* __restrict__ dst, int* deg) {
    int e = blockIdx.x * blockDim.x + threadIdx.x;
    if (e < N_EDGES) atomicAdd(&deg[dst[e]], 1);
}
__global__ __launch_bounds__(1024)
void scan_kernel(const int* __restrict__ deg, int* off, int* pos) {
    __shared__ int ps[1024];
    int t = threadIdx.x;
    const int CH = (N_NODES + 1023) / 1024;
    int b0 = t * CH, b1 = min(b0 + CH, N_NODES);
    int s = 0;
    for (int i = b0; i < b1; i++) s += deg[i];
    ps[t] = s;
    __syncthreads();
    for (int o = 1; o < 1024; o <<= 1) {
        int u = (t >= o) ? ps[t - o] : 0;
        __syncthreads();
        ps[t] += u;
        __syncthreads();
    }
    int run = ps[t] - s;
    for (int i = b0; i < b1; i++) {
        off[i] = run; pos[i] = run; run += deg[i];
    }
    if (t == 1023) off[N_NODES] = ps[1023];
}
__global__ void scatter_kernel(const int* __restrict__ src,
                               const int* __restrict__ dst,
                               const int* __restrict__ et,
                               int* pos, int2* edges) {
    int e = blockIdx.x * blockDim.x + threadIdx.x;
    if (e >= N_EDGES) return;
    int p = atomicAdd(&pos[dst[e]], 1);
    edges[p] = make_int2(src[e], et[e]);
}

// ------------------------- 128-pt Stockham FFT (64 threads/row) --------------
__device__ __forceinline__ void fft128(float2* b0, float2* b1, int t, float sgn,
                                       const float2* __restrict__ tw) {
    float2* src = b0;
    float2* dst = b1;
#pragma unroll
    for (int s = 0; s < 7; s++) {
        int m = 1 << s;
        int j = t >> s;
        float2 w = tw[(s << 6) + j];
        w.y *= sgn;
        float2 c0 = src[t];
        float2 c1 = src[t + 64];
        float2 sum = make_float2(c0.x + c1.x, c0.y + c1.y);
        float2 d   = make_float2(c0.x - c1.x, c0.y - c1.y);
        int idx = (t & (m - 1)) | ((t >> s) << (s + 1));
        dst[idx]     = sum;
        dst[idx + m] = cmulf(d, w);
        float2* tmp = src; src = dst; dst = tmp;
        __syncthreads();
    }
}

// forward untangle -> fp16 spectrum row (bin k stored as half2 at [k])
__device__ __forceinline__ void untangle_store_h(
    float2* Z, __half2* Srow, int t, const float2* __restrict__ wt) {
#pragma unroll
    for (int u = 0; u < 2; u++) {
        int k = t + 64 * u;
        float2 Zk = Z[k];
        float2 Zm = Z[(128 - k) & 127];
        float2 Ze = make_float2(0.5f * (Zk.x + Zm.x), 0.5f * (Zk.y - Zm.y));
        float2 d  = make_float2(Zk.x - Zm.x, Zk.y + Zm.y);
        float2 Zo = make_float2(0.5f * d.y, -0.5f * d.x);
        float2 W  = wt[k];
        float2 H  = make_float2(Ze.x + W.x * Zo.x - W.y * Zo.y,
                                Ze.y + W.x * Zo.y + W.y * Zo.x);
        Srow[k] = __float22half2_rn(H);
    }
    if (t == 0) {
        float2 Z0 = Z[0];
        Srow[128] = __float22half2_rn(make_float2(Z0.x - Z0.y, 0.f));
    }
}

// ------------------------- gather + forward rfft (fused) ---------------------
__global__ __launch_bounds__(256)
void gather_fft_kernel(const int* __restrict__ x, const float* __restrict__ emb,
                       float* __restrict__ h, __half2* __restrict__ hH,
                       __half2* __restrict__ SH,
                       const float2* __restrict__ tw, const float2* __restrict__ wt) {
    __shared__ float2 buf[4][2][128];
    int g = threadIdx.x >> 6, t = threadIdx.x & 63;
    int row = (blockIdx.x << 2) + g;
    float4 v = reinterpret_cast<const float4*>(emb + (size_t)x[row] * DIM)[t];
    reinterpret_cast<float4*>(h + (size_t)row * DIM)[t] = v;
    __half2 p0 = __float22half2_rn(make_float2(v.x, v.y));
    __half2 p1 = __float22half2_rn(make_float2(v.z, v.w));
    *reinterpret_cast<uint2*>(hH + (size_t)row * HROW2 + 2 * t) =
        make_uint2(*reinterpret_cast<uint32_t*>(&p0), *reinterpret_cast<uint32_t*>(&p1));
    buf[g][0][2 * t]     = make_float2(v.x, v.y);
    buf[g][0][2 * t + 1] = make_float2(v.z, v.w);
    __syncthreads();
    fft128(buf[g][0], buf[g][1], t, -1.f, tw);
    untangle_store_h(buf[g][1], SH + (size_t)row * SROW2, t, wt);
}

// ------------------------- rel table fft -> fp16 copies ----------------------
__global__ __launch_bounds__(256)
void rel_fft_kernel(const float* __restrict__ rel, __half2* __restrict__ rH,
                    __half2* __restrict__ RSH,
                    const float2* __restrict__ tw, const float2* __restrict__ wt) {
    __shared__ float2 buf[4][2][128];
    int g = threadIdx.x >> 6, t = threadIdx.x & 63;
    int row = (blockIdx.x << 2) + g;
    float4 v = reinterpret_cast<const float4*>(rel + (size_t)row * DIM)[t];
    __half2 p0 = __float22half2_rn(make_float2(v.x, v.y));
    __half2 p1 = __float22half2_rn(make_float2(v.z, v.w));
    *reinterpret_cast<uint2*>(rH + (size_t)row * HROW2 + 2 * t) =
        make_uint2(*reinterpret_cast<uint32_t*>(&p0), *reinterpret_cast<uint32_t*>(&p1));
    buf[g][0][2 * t]     = make_float2(v.x, v.y);
    buf[g][0][2 * t + 1] = make_float2(v.z, v.w);
    __syncthreads();
    fft128(buf[g][0], buf[g][1], t, -1.f, tw);
    untangle_store_h(buf[g][1], RSH + (size_t)row * SROW2, t, wt);
}

// --------------- aggregation + inverse rfft (fused, fp16 gathers) ------------
__global__ __launch_bounds__(256)
void agg_inv_kernel(const int2* __restrict__ edges, const int* __restrict__ off,
                    const __half2* __restrict__ hH,  const __half2* __restrict__ HSH,
                    const __half2* __restrict__ rH, const __half2* __restrict__ RSH,
                    const float* __restrict__ w, int wofs,
                    float* __restrict__ HC,
                    const float2* __restrict__ tw, const float2* __restrict__ wi) {
    __shared__ float2 buf[4][2][128];
    __shared__ float2 sA[4][132];
    int g = threadIdx.x >> 6, t = threadIdx.x & 63;
    int v = (blockIdx.x << 2) + g;
    float w0 = w[wofs + 0], w1 = w[wofs + 1], w2 = w[wofs + 2];

    // self-loop (rel type 0)
    float4 T = comb4(ldh4(hH + (size_t)v * HROW2, t), ldh4(rH, t), w0, w1);
    float4 F = spec4(ldh4(HSH + (size_t)v * SROW2, t), ldh4(RSH, t));
    float2 Ft = make_float2(0.f, 0.f);
    if (t == 0) {
        float2 a = __half22float2(HSH[(size_t)v * SROW2 + 128]);
        float2 b = __half22float2(RSH[128]);
        Ft = make_float2(a.x * b.x + a.y * b.y, a.y * b.x - a.x * b.y);
    }

    int e0 = off[v], e1 = off[v + 1];
    for (int e = e0; e < e1; e++) {
        int2 ed = edges[e];
        const __half2* hr = hH  + (size_t)ed.x * HROW2;
        const __half2* rr = rH  + (size_t)ed.y * HROW2;
        const __half2* sr = HSH + (size_t)ed.x * SROW2;
        const __half2* tr = RSH + (size_t)ed.y * SROW2;
        T = add4(T, comb4(ldh4(hr, t), ldh4(rr, t), w0, w1));
        F = add4(F, spec4(ldh4(sr, t), ldh4(tr, t)));
        if (t == 0) {
            float2 a = __half22float2(sr[128]);
            float2 b = __half22float2(tr[128]);
            Ft.x += a.x * b.x + a.y * b.y;
            Ft.y += a.y * b.x - a.x * b.y;
        }
    }

    // stage spectrum (scaled by w2) into shared
    sA[g][2 * t]     = make_float2(w2 * F.x, w2 * F.y);
    sA[g][2 * t + 1] = make_float2(w2 * F.z, w2 * F.w);
    if (t == 0) sA[g][128] = make_float2(w2 * Ft.x, w2 * Ft.y);
    __syncthreads();

    // inverse untangle -> packed complex
#pragma unroll
    for (int u = 0; u < 2; u++) {
        int k = t + 64 * u;
        float2 Ak = sA[g][k], Am = sA[g][128 - k];
        float2 Ze = make_float2(0.5f * (Ak.x + Am.x), 0.5f * (Ak.y - Am.y));
        float2 hd = make_float2(0.5f * (Ak.x - Am.x), 0.5f * (Ak.y + Am.y));
        float2 Zo = cmulf(wi[k], hd);
        buf[g][0][k] = make_float2(Ze.x - Zo.y, Ze.y + Zo.x);
    }
    __syncthreads();
    fft128(buf[g][0], buf[g][1], t, +1.f, tw);
    float2 z0 = buf[g][1][2 * t], z1 = buf[g][1][2 * t + 1];
    const float inv = 1.f / 128.f;
    float4 o = make_float4(T.x + z0.x * inv, T.y + z0.y * inv,
                           T.z + z1.x * inv, T.w + z1.y * inv);
    reinterpret_cast<float4*>(HC + (size_t)v * DIM)[t] = o;
}

// --------- LN + ReLU (input Z already = gemm+bias+resid), optional fft -------
template<bool DO_FFT>
__global__ __launch_bounds__(256)
void epilogue_fft_kernel(const float* __restrict__ Z,
                         const float* __restrict__ gamma,
                         const float* __restrict__ beta,
                         float* __restrict__ h_out,
                         __half2* __restrict__ hH,
                         __half2* __restrict__ SH,
                         const float2* __restrict__ tw,
                         const float2* __restrict__ wt) {
    __shared__ float2 buf[4][2][128];
    __shared__ float sred[4][2];
    int g = threadIdx.x >> 6, t = threadIdx.x & 63;
    int wsub = t >> 5;
    int v = (blockIdx.x << 2) + g;

    float4 z = reinterpret_cast<const float4*>(Z + (size_t)v * DIM)[t];
    float s = z.x + z.y + z.z + z.w;
#pragma unroll
    for (int ofs = 16; ofs; ofs >>= 1) s += __shfl_xor_sync(0xffffffffu, s, ofs);
    if ((t & 31) == 0) sred[g][wsub] = s;
    __syncthreads();
    float mu = (sred[g][0] + sred[g][1]) * (1.f / DIM);
    __syncthreads();
    float4 zc = make_float4(z.x - mu, z.y - mu, z.z - mu, z.w - mu);
    float vv = zc.x * zc.x + zc.y * zc.y + zc.z * zc.z + zc.w * zc.w;
#pragma unroll
    for (int ofs = 16; ofs; ofs >>= 1) vv += __shfl_xor_sync(0xffffffffu, vv, ofs);
    if ((t & 31) == 0) sred[g][wsub] = vv;
    __syncthreads();
    float rstd = rsqrtf((sred[g][0] + sred[g][1]) * (1.f / DIM) + LN_EPS);
    float4 gm = reinterpret_cast<const float4*>(gamma)[t];
    float4 bt = reinterpret_cast<const float4*>(beta)[t];
    float4 y = make_float4(fmaxf(zc.x * rstd * gm.x + bt.x, 0.f),
                           fmaxf(zc.y * rstd * gm.y + bt.y, 0.f),
                           fmaxf(zc.z * rstd * gm.z + bt.z, 0.f),
                           fmaxf(zc.w * rstd * gm.w + bt.w, 0.f));
    reinterpret_cast<float4*>(h_out + (size_t)v * DIM)[t] = y;
    if (DO_FFT) {
        __half2 p0 = __float22half2_rn(make_float2(y.x, y.y));
        __half2 p1 = __float22half2_rn(make_float2(y.z, y.w));
        *reinterpret_cast<uint2*>(hH + (size_t)v * HROW2 + 2 * t) =
            make_uint2(*reinterpret_cast<uint32_t*>(&p0), *reinterpret_cast<uint32_t*>(&p1));
        buf[g][0][2 * t]     = make_float2(y.x, y.y);
        buf[g][0][2 * t + 1] = make_float2(y.z, y.w);
        __syncthreads();
        fft128(buf[g][0], buf[g][1], t, -1.f, tw);
        untangle_store_h(buf[g][1], SH + (size_t)v * SROW2, t, wt);
    }
}

// ------------------------- bf16x3 tensor-core GEMM ---------------------------
// C[m,n] = sum_k A[m,k]*B[n,k]  (+ bias[n])  (+ Hres[m,n])
#define GBK 32
#define GPAD 2

__device__ __forceinline__ void mma_bf16(float* d,
    uint32_t a0, uint32_t a1, uint32_t a2, uint32_t a3,
    uint32_t b0, uint32_t b1) {
    asm volatile(
        "mma.sync.aligned.m16n8k16.row.col.f32.bf16.bf16.f32 "
        "{%0,%1,%2,%3}, {%4,%5,%6,%7}, {%8,%9}, {%0,%1,%2,%3};"
        : "+f"(d[0]), "+f"(d[1]), "+f"(d[2]), "+f"(d[3])
        : "r"(a0), "r"(a1), "r"(a2), "r"(a3), "r"(b0), "r"(b1));
}

template<bool BIAS, bool RESID>
__global__ __launch_bounds__(256)
void bf16x3_gemm(const float* __restrict__ A, const float* __restrict__ B,
                 float* __restrict__ C, const float* __restrict__ bias,
                 const float* __restrict__ Hres,
                 int M, int N, int K) {
    __shared__ __align__(16) __nv_bfloat16 Ah[128][GBK + GPAD];
    __shared__ __align__(16) __nv_bfloat16 Al[128][GBK + GPAD];
    __shared__ __align__(16) __nv_bfloat16 Bh[128][GBK + GPAD];
    __shared__ __align__(16) __nv_bfloat16 Bl[128][GBK + GPAD];

    int tid = threadIdx.x;
    int lane = tid & 31, wid = tid >> 5;
    int wm = wid & 1, wn = wid >> 1;
    int r = lane >> 2, cq = lane & 3;
    int bm = blockIdx.y * 128, bn = blockIdx.x * 128;

    float acc[4][4][4];
#pragma unroll
    for (int a = 0; a < 4; a++)
#pragma unroll
        for (int b = 0; b < 4; b++)
#pragma unroll
            for (int c = 0; c < 4; c++) acc[a][b][c] = 0.f;

    for (int k0 = 0; k0 < K; k0 += GBK) {
#pragma unroll
        for (int i = 0; i < 4; i++) {
            int idx = tid + 256 * i;
            int row = idx >> 3, kc = (idx & 7) << 2;
            float4 av = make_float4(0.f, 0.f, 0.f, 0.f);
            if (bm + row < M)
                av = *reinterpret_cast<const float4*>(A + (size_t)(bm + row) * K + k0 + kc);
            float fx[4] = {av.x, av.y, av.z, av.w};
#pragma unroll
            for (int j = 0; j < 4; j++) {
                __nv_bfloat16 hi = __float2bfloat16(fx[j]);
                Ah[row][kc + j] = hi;
                Al[row][kc + j] = __float2bfloat16(fx[j] - __bfloat162float(hi));
            }
            float4 bv = make_float4(0.f, 0.f, 0.f, 0.f);
            if (bn + row < N)
                bv = *reinterpret_cast<const float4*>(B + (size_t)(bn + row) * K + k0 + kc);
            float gx[4] = {bv.x, bv.y, bv.z, bv.w};
#pragma unroll
            for (int j = 0; j < 4; j++) {
                __nv_bfloat16 hi = __float2bfloat16(gx[j]);
                Bh[row][kc + j] = hi;
                Bl[row][kc + j] = __float2bfloat16(gx[j] - __bfloat162float(hi));
            }
        }
        __syncthreads();

#pragma unroll
        for (int ks = 0; ks < 2; ks++) {
            int kb = ks * 16 + cq * 2;
            uint32_t bhf[4][2], blf[4][2];
#pragma unroll
            for (int nf = 0; nf < 4; nf++) {
                int col = wn * 32 + nf * 8 + r;
                bhf[nf][0] = *reinterpret_cast<const uint32_t*>(&Bh[col][kb]);
                bhf[nf][1] = *reinterpret_cast<const uint32_t*>(&Bh[col][kb + 8]);
                blf[nf][0] = *reinterpret_cast<const uint32_t*>(&Bl[col][kb]);
                blf[nf][1] = *reinterpret_cast<const uint32_t*>(&Bl[col][kb + 8]);
            }
#pragma unroll
            for (int mf = 0; mf < 4; mf++) {
                int row = wm * 64 + mf * 16 + r;
                uint32_t a0 = *reinterpret_cast<const uint32_t*>(&Ah[row][kb]);
                uint32_t a1 = *reinterpret_cast<const uint32_t*>(&Ah[row + 8][kb]);
                uint32_t a2 = *reinterpret_cast<const uint32_t*>(&Ah[row][kb + 8]);
                uint32_t a3 = *reinterpret_cast<const uint32_t*>(&Ah[row + 8][kb + 8]);
                uint32_t l0 = *reinterpret_cast<const uint32_t*>(&Al[row][kb]);
                uint32_t l1 = *reinterpret_cast<const uint32_t*>(&Al[row + 8][kb]);
                uint32_t l2 = *reinterpret_cast<const uint32_t*>(&Al[row][kb + 8]);
                uint32_t l3 = *reinterpret_cast<const uint32_t*>(&Al[row + 8][kb + 8]);
#pragma unroll
                for (int nf = 0; nf < 4; nf++) {
                    mma_bf16(acc[mf][nf], a0, a1, a2, a3, bhf[nf][0], bhf[nf][1]);
                    mma_bf16(acc[mf][nf], a0, a1, a2, a3, blf[nf][0], blf[nf][1]);
                    mma_bf16(acc[mf][nf], l0, l1, l2, l3, bhf[nf][0], bhf[nf][1]);
                }
            }
        }
        __syncthreads();
    }

#pragma unroll
    for (int mf = 0; mf < 4; mf++) {
        int row0 = bm + wm * 64 + mf * 16 + r;
#pragma unroll
        for (int nf = 0; nf < 4; nf++) {
            int col = bn + wn * 32 + nf * 8 + cq * 2;
            float bx = 0.f, by = 0.f;
            if (BIAS) { bx = bias[col]; by = bias[col + 1]; }
            if (row0 < M) {
                float rx = bx, ry = by;
                if (RESID) {
                    float2 hv = *reinterpret_cast<const float2*>(
                        Hres + (size_t)row0 * N + col);
                    rx += hv.x; ry += hv.y;
                }
                *reinterpret_cast<float2*>(C + (size_t)row0 * N + col) =
                    make_float2(acc[mf][nf][0] + rx, acc[mf][nf][1] + ry);
            }
            if (row0 + 8 < M) {
                float rx = bx, ry = by;
                if (RESID) {
                    float2 hv = *reinterpret_cast<const float2*>(
                        Hres + (size_t)(row0 + 8) * N + col);
                    rx += hv.x; ry += hv.y;
                }
                *reinterpret_cast<float2*>(C + (size_t)(row0 + 8) * N + col) =
                    make_float2(acc[mf][nf][2] + rx, acc[mf][nf][3] + ry);
            }
        }
    }
}

// ------------------------- launch --------------------------------------------
extern "C" void kernel_launch(void* const* d_in, const int* in_sizes, int n_in,
                              void* d_out, int out_size) {
    (void)in_sizes; (void)n_in; (void)out_size;
    const int*   x    = (const int*)  d_in[0];
    const int*   eidx = (const int*)  d_in[1];
    const int*   et   = (const int*)  d_in[2];
    const float* emb  = (const float*)d_in[3];
    const float* rel1 = (const float*)d_in[4];
    const float* Wn1  = (const float*)d_in[7];
    const float* bn1  = (const float*)d_in[8];
    const float* cw1  = (const float*)d_in[9];
    const float* gm1  = (const float*)d_in[10];
    const float* bt1  = (const float*)d_in[11];
    const float* rel2 = (const float*)d_in[12];
    const float* Wr2  = (const float*)d_in[13];
    const float* br2  = (const float*)d_in[14];
    const float* Wn2  = (const float*)d_in[15];
    const float* bn2  = (const float*)d_in[16];
    const float* cw2  = (const float*)d_in[17];
    const float* gm2  = (const float*)d_in[18];
    const float* bt2  = (const float*)d_in[19];

    float* out_h    = (float*)d_out;
    float* out_rels = out_h + (size_t)N_NODES * DIM;
    const int* src = eidx;
    const int* dst = eidx + N_EDGES;

    float *pH, *pHC, *pZ, *pTw, *pWt, *pWi, *pW;
    __half2 *pHH, *pHSH, *pRH, *pRSH;
    int *pDeg, *pOff, *pPos;
    int2* pEdges;
    cudaGetSymbolAddress((void**)&pH,    g_h);
    cudaGetSymbolAddress((void**)&pHC,   g_HC);
    cudaGetSymbolAddress((void**)&pZ,    g_Z);
    cudaGetSymbolAddress((void**)&pHH,   g_hH);
    cudaGetSymbolAddress((void**)&pHSH,  g_HSH);
    cudaGetSymbolAddress((void**)&pRH,   g_rH);
    cudaGetSymbolAddress((void**)&pRSH,  g_RSH);
    cudaGetSymbolAddress((void**)&pTw,   g_tw);
    cudaGetSymbolAddress((void**)&pWt,   g_wt);
    cudaGetSymbolAddress((void**)&pWi,   g_wi);
    cudaGetSymbolAddress((void**)&pW,    g_w);
    cudaGetSymbolAddress((void**)&pDeg,  g_deg);
    cudaGetSymbolAddress((void**)&pOff,  g_off);
    cudaGetSymbolAddress((void**)&pPos,  g_pos);
    cudaGetSymbolAddress((void**)&pEdges, g_edges);

    const float2* tw = (const float2*)pTw;
    const float2* wt = (const float2*)pWt;
    const float2* wi = (const float2*)pWi;

    setup_kernel<<<(N_NODES + 255) / 256, 256>>>(pTw, pWt, pWi, cw1, cw2, pW, pDeg);
    hist_kernel<<<(N_EDGES + 255) / 256, 256>>>(dst, pDeg);
    scan_kernel<<<1, 1024>>>(pDeg, pOff, pPos);
    scatter_kernel<<<(N_EDGES + 255) / 256, 256>>>(src, dst, et, pPos, pEdges);

    gather_fft_kernel<<<N_NODES / 4, 256>>>(x, emb, pH, pHH, pHSH, tw, wt);

    for (int L = 0; L < 2; L++) {
        const float* rel = (L == 0) ? rel1 : rel2;
        const float* Wn  = (L == 0) ? Wn1  : Wn2;
        const float* bn  = (L == 0) ? bn1  : bn2;
        const float* gm  = (L == 0) ? gm1  : gm2;
        const float* bt  = (L == 0) ? bt1  : bt2;

        rel_fft_kernel<<<NRELS / 4, 256>>>(rel, pRH, pRSH, tw, wt);
        agg_inv_kernel<<<N_NODES / 4, 256>>>(pEdges, pOff, pHH, pHSH, pRH, pRSH,
                                             pW, 3 * L, pHC, tw, wi);
        // Z = HC @ Wn^T + bn + h   (residual fused)
        bf16x3_gemm<true, true><<<dim3(2, (N_NODES + 127) / 128), 256>>>(
            pHC, Wn, pZ, bn, pH, N_NODES, DIM, DIM);
        if (L == 0) {
            epilogue_fft_kernel<true><<<N_NODES / 4, 256>>>(
                pZ, gm, bt, pH, pHH, pHSH, tw, wt);
        } else {
            epilogue_fft_kernel<false><<<N_NODES / 4, 256>>>(
                pZ, gm, bt, out_h, nullptr, nullptr, tw, wt);
        }
    }

    bf16x3_gemm<true, false><<<dim3(2, (NRELS + 127) / 128), 256>>>(
        rel2, Wr2, out_rels, br2, nullptr, NRELS, DIM, DIM);
}

// round 6
// speedup vs baseline: 3.0214x; 1.0764x over previous
#include <cuda_runtime.h>
#include <cuda_bf16.h>
#include <cuda_fp16.h>
#include <math.h>
#include <stdint.h>

#define N_NODES 50000
#define N_EDGES 250000
#define DIM     256
#define NRELS   400
#define HROW2   128     // h row: 128 half2 (256 vals) = 512 B
#define SROW2   130     // spec row: 129 complex bins as half2 + 1 pad = 520 B
#define LN_EPS  1e-5f

// ------------------------- scratch (device globals) --------------------------
__device__ float   g_h  [(size_t)N_NODES * DIM];     // fp32 h (residual path)
__device__ float   g_HC [(size_t)N_NODES * DIM];     // aggT + irfft(aggF)
__device__ float   g_Z  [(size_t)N_NODES * DIM];     // gemm out + bias + resid
__device__ __half2 g_hH [(size_t)N_NODES * HROW2];   // h as fp16
__device__ __half2 g_HSH[(size_t)N_NODES * SROW2];   // rfft(h) as fp16
__device__ __half2 g_rH [2][(size_t)NRELS * HROW2];  // rel as fp16 (per layer)
__device__ __half2 g_RSH[2][(size_t)NRELS * SROW2];  // rfft(rel) as fp16
__device__ float   g_tw [7 * 64 * 2];
__device__ float   g_wt [129 * 2];
__device__ float   g_wi [129 * 2];
__device__ float   g_w  [6];
__device__ int     g_deg[N_NODES];
__device__ int     g_off[N_NODES + 1];
__device__ int     g_pos[N_NODES];
__device__ int2    g_edges[N_EDGES];                 // (src, et) sorted by dst

// ------------------------- small helpers -------------------------------------
__device__ __forceinline__ float2 cmulf(float2 a, float2 b) {
    return make_float2(a.x * b.x - a.y * b.y, a.x * b.y + a.y * b.x);
}
__device__ __forceinline__ float4 comb4(float4 a, float4 b, float w0, float w1) {
    return make_float4(w0 * a.x * b.x + w1 * (a.x + b.x),
                       w0 * a.y * b.y + w1 * (a.y + b.y),
                       w0 * a.z * b.z + w1 * (a.z + b.z),
                       w0 * a.w * b.w + w1 * (a.w + b.w));
}
__device__ __forceinline__ float4 spec4(float4 a, float4 b) {
    return make_float4(a.x * b.x + a.y * b.y,
                       a.y * b.x - a.x * b.y,
                       a.z * b.z + a.w * b.w,
                       a.w * b.z - a.z * b.w);
}
__device__ __forceinline__ float4 add4(float4 a, float4 b) {
    return make_float4(a.x + b.x, a.y + b.y, a.z + b.z, a.w + b.w);
}
__device__ __forceinline__ float4 h2f4(uint2 raw) {
    float2 lo = __half22float2(*reinterpret_cast<__half2*>(&raw.x));
    float2 hi = __half22float2(*reinterpret_cast<__half2*>(&raw.y));
    return make_float4(lo.x, lo.y, hi.x, hi.y);
}

// ------------------------- fused setup kernel --------------------------------
__global__ void setup_kernel(float* tw, float* wt, float* wi,
                             const float* __restrict__ cw1,
                             const float* __restrict__ cw2, float* w,
                             int* deg) {
    int i = blockIdx.x * blockDim.x + threadIdx.x;
    if (i < 7 * 64) {
        int s = i >> 6, j = i & 63;
        int l = 64 >> s;
        float2 v = make_float2(0.f, 0.f);
        if (j < l) {
            double a = (double)j / (double)l;
            v = make_float2((float)cospi(a), (float)sinpi(a));
        }
        reinterpret_cast<float2*>(tw)[i] = v;
    }
    if (i < 129) {
        double a = (double)i / 128.0;
        reinterpret_cast<float2*>(wt)[i] = make_float2((float)cospi(a), (float)(-sinpi(a)));
        reinterpret_cast<float2*>(wi)[i] = make_float2((float)cospi(a), (float)( sinpi(a)));
    }
    if (i == 0) {
        for (int L = 0; L < 2; L++) {
            const float* c = (L == 0) ? cw1 : cw2;
            float m = fmaxf(c[0], fmaxf(c[1], c[2]));
            float e0 = expf(c[0] - m), e1 = expf(c[1] - m), e2 = expf(c[2] - m);
            float s = e0 + e1 + e2;
            w[L * 3 + 0] = e0 / s; w[L * 3 + 1] = e1 / s; w[L * 3 + 2] = e2 / s;
        }
    }
    if (i < N_NODES) deg[i] = 0;
}

// ------------------------- edge sorting (counting sort by dst) ---------------
__global__ void hist_kernel(const int* __restrict__ dst, int* deg) {
    int e = blockIdx.x * blockDim.x + threadIdx.x;
    if (e < N_EDGES) atomicAdd(&deg[dst[e]], 1);
}
__global__ __launch_bounds__(1024)
void scan_kernel(const int* __restrict__ deg, int* off, int* pos) {
    __shared__ int ps[1024];
    int t = threadIdx.x;
    const int CH = (N_NODES + 1023) / 1024;
    int b0 = t * CH, b1 = min(b0 + CH, N_NODES);
    int s = 0;
    for (int i = b0; i < b1; i++) s += deg[i];
    ps[t] = s;
    __syncthreads();
    for (int o = 1; o < 1024; o <<= 1) {
        int u = (t >= o) ? ps[t - o] : 0;
        __syncthreads();
        ps[t] += u;
        __syncthreads();
    }
    int run = ps[t] - s;
    for (int i = b0; i < b1; i++) {
        off[i] = run; pos[i] = run; run += deg[i];
    }
    if (t == 1023) off[N_NODES] = ps[1023];
}
__global__ void scatter_kernel(const int* __restrict__ src,
                               const int* __restrict__ dst,
                               const int* __restrict__ et,
                               int* pos, int2* edges) {
    int e = blockIdx.x * blockDim.x + threadIdx.x;
    if (e >= N_EDGES) return;
    int p = atomicAdd(&pos[dst[e]], 1);
    edges[p] = make_int2(src[e], et[e]);
}

// ------------------------- 128-pt Stockham FFT (64 threads/row) --------------
__device__ __forceinline__ void fft128(float2* b0, float2* b1, int t, float sgn,
                                       const float2* __restrict__ tw) {
    float2* src = b0;
    float2* dst = b1;
#pragma unroll
    for (int s = 0; s < 7; s++) {
        int m = 1 << s;
        int j = t >> s;
        float2 w = tw[(s << 6) + j];
        w.y *= sgn;
        float2 c0 = src[t];
        float2 c1 = src[t + 64];
        float2 sum = make_float2(c0.x + c1.x, c0.y + c1.y);
        float2 d   = make_float2(c0.x - c1.x, c0.y - c1.y);
        int idx = (t & (m - 1)) | ((t >> s) << (s + 1));
        dst[idx]     = sum;
        dst[idx + m] = cmulf(d, w);
        float2* tmp = src; src = dst; dst = tmp;
        __syncthreads();
    }
}

// forward untangle -> fp16 spectrum row
__device__ __forceinline__ void untangle_store_h(
    float2* Z, __half2* Srow, int t, const float2* __restrict__ wt) {
#pragma unroll
    for (int u = 0; u < 2; u++) {
        int k = t + 64 * u;
        float2 Zk = Z[k];
        float2 Zm = Z[(128 - k) & 127];
        float2 Ze = make_float2(0.5f * (Zk.x + Zm.x), 0.5f * (Zk.y - Zm.y));
        float2 d  = make_float2(Zk.x - Zm.x, Zk.y + Zm.y);
        float2 Zo = make_float2(0.5f * d.y, -0.5f * d.x);
        float2 W  = wt[k];
        float2 H  = make_float2(Ze.x + W.x * Zo.x - W.y * Zo.y,
                                Ze.y + W.x * Zo.y + W.y * Zo.x);
        Srow[k] = __float22half2_rn(H);
    }
    if (t == 0) {
        float2 Z0 = Z[0];
        Srow[128] = __float22half2_rn(make_float2(Z0.x - Z0.y, 0.f));
    }
}

// ------------------------- gather + forward rfft (fused) ---------------------
__global__ __launch_bounds__(256)
void gather_fft_kernel(const int* __restrict__ x, const float* __restrict__ emb,
                       float* __restrict__ h, __half2* __restrict__ hH,
                       __half2* __restrict__ SH,
                       const float2* __restrict__ tw, const float2* __restrict__ wt) {
    __shared__ float2 buf[4][2][128];
    int g = threadIdx.x >> 6, t = threadIdx.x & 63;
    int row = (blockIdx.x << 2) + g;
    float4 v = reinterpret_cast<const float4*>(emb + (size_t)x[row] * DIM)[t];
    reinterpret_cast<float4*>(h + (size_t)row * DIM)[t] = v;
    __half2 p0 = __float22half2_rn(make_float2(v.x, v.y));
    __half2 p1 = __float22half2_rn(make_float2(v.z, v.w));
    *reinterpret_cast<uint2*>(hH + (size_t)row * HROW2 + 2 * t) =
        make_uint2(*reinterpret_cast<uint32_t*>(&p0), *reinterpret_cast<uint32_t*>(&p1));
    buf[g][0][2 * t]     = make_float2(v.x, v.y);
    buf[g][0][2 * t + 1] = make_float2(v.z, v.w);
    __syncthreads();
    fft128(buf[g][0], buf[g][1], t, -1.f, tw);
    untangle_store_h(buf[g][1], SH + (size_t)row * SROW2, t, wt);
}

// ------------------------- rel table fft -> fp16 copies ----------------------
__global__ __launch_bounds__(256)
void rel_fft_kernel(const float* __restrict__ rel, __half2* __restrict__ rH,
                    __half2* __restrict__ RSH,
                    const float2* __restrict__ tw, const float2* __restrict__ wt) {
    __shared__ float2 buf[4][2][128];
    int g = threadIdx.x >> 6, t = threadIdx.x & 63;
    int row = (blockIdx.x << 2) + g;
    float4 v = reinterpret_cast<const float4*>(rel + (size_t)row * DIM)[t];
    __half2 p0 = __float22half2_rn(make_float2(v.x, v.y));
    __half2 p1 = __float22half2_rn(make_float2(v.z, v.w));
    *reinterpret_cast<uint2*>(rH + (size_t)row * HROW2 + 2 * t) =
        make_uint2(*reinterpret_cast<uint32_t*>(&p0), *reinterpret_cast<uint32_t*>(&p1));
    buf[g][0][2 * t]     = make_float2(v.x, v.y);
    buf[g][0][2 * t + 1] = make_float2(v.z, v.w);
    __syncthreads();
    fft128(buf[g][0], buf[g][1], t, -1.f, tw);
    untangle_store_h(buf[g][1], RSH + (size_t)row * SROW2, t, wt);
}

// --------------- aggregation + inverse rfft (fused, x2-unrolled) -------------
__global__ __launch_bounds__(256)
void agg_inv_kernel(const int2* __restrict__ edges, const int* __restrict__ off,
                    const __half2* __restrict__ hH,  const __half2* __restrict__ HSH,
                    const __half2* __restrict__ rH, const __half2* __restrict__ RSH,
                    const float* __restrict__ w, int wofs,
                    float* __restrict__ HC,
                    const float2* __restrict__ tw, const float2* __restrict__ wi) {
    __shared__ float2 buf[4][2][128];
    __shared__ float2 sA[4][132];
    int g = threadIdx.x >> 6, t = threadIdx.x & 63;
    int v = (blockIdx.x << 2) + g;
    float w0 = w[wofs + 0], w1 = w[wofs + 1], w2 = w[wofs + 2];

    const uint2* hHu  = reinterpret_cast<const uint2*>(hH);
    const uint2* rHu  = reinterpret_cast<const uint2*>(rH);
    const uint2* HSHu = reinterpret_cast<const uint2*>(HSH);
    const uint2* RSHu = reinterpret_cast<const uint2*>(RSH);

    // self-loop (rel type 0)
    float4 T = comb4(h2f4(hHu[(size_t)v * 64 + t]), h2f4(rHu[t]), w0, w1);
    float4 F = spec4(h2f4(HSHu[(size_t)v * 65 + t]), h2f4(RSHu[t]));
    float2 Ft = make_float2(0.f, 0.f);
    if (t == 0) {
        float2 a = __half22float2(HSH[(size_t)v * SROW2 + 128]);
        float2 b = __half22float2(RSH[128]);
        Ft = make_float2(a.x * b.x + a.y * b.y, a.y * b.x - a.x * b.y);
    }

    int e = off[v], e1 = off[v + 1];
    // ---- pairs: issue both edges' loads before consuming (2x MLP) ----
    for (; e + 1 < e1; e += 2) {
        int2 ea = edges[e];
        int2 eb = edges[e + 1];
        uint2 ha = hHu [(size_t)ea.x * 64 + t];
        uint2 ra = rHu [(size_t)ea.y * 64 + t];
        uint2 sa = HSHu[(size_t)ea.x * 65 + t];
        uint2 ta = RSHu[(size_t)ea.y * 65 + t];
        uint2 hb = hHu [(size_t)eb.x * 64 + t];
        uint2 rb = rHu [(size_t)eb.y * 64 + t];
        uint2 sb = HSHu[(size_t)eb.x * 65 + t];
        uint2 tb = RSHu[(size_t)eb.y * 65 + t];
        T = add4(T, comb4(h2f4(ha), h2f4(ra), w0, w1));
        F = add4(F, spec4(h2f4(sa), h2f4(ta)));
        T = add4(T, comb4(h2f4(hb), h2f4(rb), w0, w1));
        F = add4(F, spec4(h2f4(sb), h2f4(tb)));
        if (t == 0) {
            float2 a0 = __half22float2(HSH[(size_t)ea.x * SROW2 + 128]);
            float2 b0 = __half22float2(RSH[(size_t)ea.y * SROW2 + 128]);
            float2 a1 = __half22float2(HSH[(size_t)eb.x * SROW2 + 128]);
            float2 b1 = __half22float2(RSH[(size_t)eb.y * SROW2 + 128]);
            Ft.x += a0.x * b0.x + a0.y * b0.y + a1.x * b1.x + a1.y * b1.y;
            Ft.y += a0.y * b0.x - a0.x * b0.y + a1.y * b1.x - a1.x * b1.y;
        }
    }
    if (e < e1) {
        int2 ed = edges[e];
        T = add4(T, comb4(h2f4(hHu[(size_t)ed.x * 64 + t]),
                          h2f4(rHu[(size_t)ed.y * 64 + t]), w0, w1));
        F = add4(F, spec4(h2f4(HSHu[(size_t)ed.x * 65 + t]),
                          h2f4(RSHu[(size_t)ed.y * 65 + t])));
        if (t == 0) {
            float2 a = __half22float2(HSH[(size_t)ed.x * SROW2 + 128]);
            float2 b = __half22float2(RSH[(size_t)ed.y * SROW2 + 128]);
            Ft.x += a.x * b.x + a.y * b.y;
            Ft.y += a.y * b.x - a.x * b.y;
        }
    }

    // stage spectrum (scaled by w2) into shared
    sA[g][2 * t]     = make_float2(w2 * F.x, w2 * F.y);
    sA[g][2 * t + 1] = make_float2(w2 * F.z, w2 * F.w);
    if (t == 0) sA[g][128] = make_float2(w2 * Ft.x, w2 * Ft.y);
    __syncthreads();

    // inverse untangle -> packed complex
#pragma unroll
    for (int u = 0; u < 2; u++) {
        int k = t + 64 * u;
        float2 Ak = sA[g][k], Am = sA[g][128 - k];
        float2 Ze = make_float2(0.5f * (Ak.x + Am.x), 0.5f * (Ak.y - Am.y));
        float2 hd = make_float2(0.5f * (Ak.x - Am.x), 0.5f * (Ak.y + Am.y));
        float2 Zo = cmulf(wi[k], hd);
        buf[g][0][k] = make_float2(Ze.x - Zo.y, Ze.y + Zo.x);
    }
    __syncthreads();
    fft128(buf[g][0], buf[g][1], t, +1.f, tw);
    float2 z0 = buf[g][1][2 * t], z1 = buf[g][1][2 * t + 1];
    const float inv = 1.f / 128.f;
    float4 o = make_float4(T.x + z0.x * inv, T.y + z0.y * inv,
                           T.z + z1.x * inv, T.w + z1.y * inv);
    reinterpret_cast<float4*>(HC + (size_t)v * DIM)[t] = o;
}

// --------- LN + ReLU (input Z already = gemm+bias+resid), optional fft -------
template<bool DO_FFT>
__global__ __launch_bounds__(256)
void epilogue_fft_kernel(const float* __restrict__ Z,
                         const float* __restrict__ gamma,
                         const float* __restrict__ beta,
                         float* __restrict__ h_out,
                         __half2* __restrict__ hH,
                         __half2* __restrict__ SH,
                         const float2* __restrict__ tw,
                         const float2* __restrict__ wt) {
    __shared__ float2 buf[4][2][128];
    __shared__ float sred[4][2];
    int g = threadIdx.x >> 6, t = threadIdx.x & 63;
    int wsub = t >> 5;
    int v = (blockIdx.x << 2) + g;

    float4 z = reinterpret_cast<const float4*>(Z + (size_t)v * DIM)[t];
    float s = z.x + z.y + z.z + z.w;
#pragma unroll
    for (int ofs = 16; ofs; ofs >>= 1) s += __shfl_xor_sync(0xffffffffu, s, ofs);
    if ((t & 31) == 0) sred[g][wsub] = s;
    __syncthreads();
    float mu = (sred[g][0] + sred[g][1]) * (1.f / DIM);
    __syncthreads();
    float4 zc = make_float4(z.x - mu, z.y - mu, z.z - mu, z.w - mu);
    float vv = zc.x * zc.x + zc.y * zc.y + zc.z * zc.z + zc.w * zc.w;
#pragma unroll
    for (int ofs = 16; ofs; ofs >>= 1) vv += __shfl_xor_sync(0xffffffffu, vv, ofs);
    if ((t & 31) == 0) sred[g][wsub] = vv;
    __syncthreads();
    float rstd = rsqrtf((sred[g][0] + sred[g][1]) * (1.f / DIM) + LN_EPS);
    float4 gm = reinterpret_cast<const float4*>(gamma)[t];
    float4 bt = reinterpret_cast<const float4*>(beta)[t];
    float4 y = make_float4(fmaxf(zc.x * rstd * gm.x + bt.x, 0.f),
                           fmaxf(zc.y * rstd * gm.y + bt.y, 0.f),
                           fmaxf(zc.z * rstd * gm.z + bt.z, 0.f),
                           fmaxf(zc.w * rstd * gm.w + bt.w, 0.f));
    reinterpret_cast<float4*>(h_out + (size_t)v * DIM)[t] = y;
    if (DO_FFT) {
        __half2 p0 = __float22half2_rn(make_float2(y.x, y.y));
        __half2 p1 = __float22half2_rn(make_float2(y.z, y.w));
        *reinterpret_cast<uint2*>(hH + (size_t)v * HROW2 + 2 * t) =
            make_uint2(*reinterpret_cast<uint32_t*>(&p0), *reinterpret_cast<uint32_t*>(&p1));
        buf[g][0][2 * t]     = make_float2(y.x, y.y);
        buf[g][0][2 * t + 1] = make_float2(y.z, y.w);
        __syncthreads();
        fft128(buf[g][0], buf[g][1], t, -1.f, tw);
        untangle_store_h(buf[g][1], SH + (size_t)v * SROW2, t, wt);
    }
}

// ------------------------- bf16x3 tensor-core GEMM (reg-pipelined) -----------
#define GBK 32
#define GPAD 2

__device__ __forceinline__ void mma_bf16(float* d,
    uint32_t a0, uint32_t a1, uint32_t a2, uint32_t a3,
    uint32_t b0, uint32_t b1) {
    asm volatile(
        "mma.sync.aligned.m16n8k16.row.col.f32.bf16.bf16.f32 "
        "{%0,%1,%2,%3}, {%4,%5,%6,%7}, {%8,%9}, {%0,%1,%2,%3};"
        : "+f"(d[0]), "+f"(d[1]), "+f"(d[2]), "+f"(d[3])
        : "r"(a0), "r"(a1), "r"(a2), "r"(a3), "r"(b0), "r"(b1));
}

template<bool BIAS, bool RESID>
__global__ __launch_bounds__(256)
void bf16x3_gemm(const float* __restrict__ A, const float* __restrict__ B,
                 float* __restrict__ C, const float* __restrict__ bias,
                 const float* __restrict__ Hres,
                 int M, int N, int K) {
    __shared__ __align__(16) __nv_bfloat16 Ah[128][GBK + GPAD];
    __shared__ __align__(16) __nv_bfloat16 Al[128][GBK + GPAD];
    __shared__ __align__(16) __nv_bfloat16 Bh[128][GBK + GPAD];
    __shared__ __align__(16) __nv_bfloat16 Bl[128][GBK + GPAD];

    int tid = threadIdx.x;
    int lane = tid & 31, wid = tid >> 5;
    int wm = wid & 1, wn = wid >> 1;
    int r = lane >> 2, cq = lane & 3;
    int bm = blockIdx.y * 128, bn = blockIdx.x * 128;

    float acc[4][4][4];
#pragma unroll
    for (int a = 0; a < 4; a++)
#pragma unroll
        for (int b = 0; b < 4; b++)
#pragma unroll
            for (int c = 0; c < 4; c++) acc[a][b][c] = 0.f;

    // per-thread load slots: 4 float4 of A, 4 float4 of B
    float4 avr[4], bvr[4];
    int lrow[4], lkc[4];
#pragma unroll
    for (int i = 0; i < 4; i++) {
        int idx = tid + 256 * i;
        lrow[i] = idx >> 3; lkc[i] = (idx & 7) << 2;
    }

    auto load_tile = [&](int k0) {
#pragma unroll
        for (int i = 0; i < 4; i++) {
            avr[i] = make_float4(0.f, 0.f, 0.f, 0.f);
            bvr[i] = make_float4(0.f, 0.f, 0.f, 0.f);
            if (bm + lrow[i] < M)
                avr[i] = *reinterpret_cast<const float4*>(
                    A + (size_t)(bm + lrow[i]) * K + k0 + lkc[i]);
            if (bn + lrow[i] < N)
                bvr[i] = *reinterpret_cast<const float4*>(
                    B + (size_t)(bn + lrow[i]) * K + k0 + lkc[i]);
        }
    };
    auto stage_tile = [&]() {
#pragma unroll
        for (int i = 0; i < 4; i++) {
            float fx[4] = {avr[i].x, avr[i].y, avr[i].z, avr[i].w};
            float gx[4] = {bvr[i].x, bvr[i].y, bvr[i].z, bvr[i].w};
#pragma unroll
            for (int j = 0; j < 4; j++) {
                __nv_bfloat16 ah = __float2bfloat16(fx[j]);
                Ah[lrow[i]][lkc[i] + j] = ah;
                Al[lrow[i]][lkc[i] + j] = __float2bfloat16(fx[j] - __bfloat162float(ah));
                __nv_bfloat16 bh = __float2bfloat16(gx[j]);
                Bh[lrow[i]][lkc[i] + j] = bh;
                Bl[lrow[i]][lkc[i] + j] = __float2bfloat16(gx[j] - __bfloat162float(bh));
            }
        }
    };

    load_tile(0);
    for (int k0 = 0; k0 < K; k0 += GBK) {
        stage_tile();
        __syncthreads();
        if (k0 + GBK < K) load_tile(k0 + GBK);   // overlap with MMAs below

#pragma unroll
        for (int ks = 0; ks < 2; ks++) {
            int kb = ks * 16 + cq * 2;
            uint32_t bhf[4][2], blf[4][2];
#pragma unroll
            for (int nf = 0; nf < 4; nf++) {
                int col = wn * 32 + nf * 8 + r;
                bhf[nf][0] = *reinterpret_cast<const uint32_t*>(&Bh[col][kb]);
                bhf[nf][1] = *reinterpret_cast<const uint32_t*>(&Bh[col][kb + 8]);
                blf[nf][0] = *reinterpret_cast<const uint32_t*>(&Bl[col][kb]);
                blf[nf][1] = *reinterpret_cast<const uint32_t*>(&Bl[col][kb + 8]);
            }
#pragma unroll
            for (int mf = 0; mf < 4; mf++) {
                int row = wm * 64 + mf * 16 + r;
                uint32_t a0 = *reinterpret_cast<const uint32_t*>(&Ah[row][kb]);
                uint32_t a1 = *reinterpret_cast<const uint32_t*>(&Ah[row + 8][kb]);
                uint32_t a2 = *reinterpret_cast<const uint32_t*>(&Ah[row][kb + 8]);
                uint32_t a3 = *reinterpret_cast<const uint32_t*>(&Ah[row + 8][kb + 8]);
                uint32_t l0 = *reinterpret_cast<const uint32_t*>(&Al[row][kb]);
                uint32_t l1 = *reinterpret_cast<const uint32_t*>(&Al[row + 8][kb]);
                uint32_t l2 = *reinterpret_cast<const uint32_t*>(&Al[row][kb + 8]);
                uint32_t l3 = *reinterpret_cast<const uint32_t*>(&Al[row + 8][kb + 8]);
#pragma unroll
                for (int nf = 0; nf < 4; nf++) {
                    mma_bf16(acc[mf][nf], a0, a1, a2, a3, bhf[nf][0], bhf[nf][1]);
                    mma_bf16(acc[mf][nf], a0, a1, a2, a3, blf[nf][0], blf[nf][1]);
                    mma_bf16(acc[mf][nf], l0, l1, l2, l3, bhf[nf][0], bhf[nf][1]);
                }
            }
        }
        __syncthreads();
    }

#pragma unroll
    for (int mf = 0; mf < 4; mf++) {
        int row0 = bm + wm * 64 + mf * 16 + r;
#pragma unroll
        for (int nf = 0; nf < 4; nf++) {
            int col = bn + wn * 32 + nf * 8 + cq * 2;
            float bx = 0.f, by = 0.f;
            if (BIAS) { bx = bias[col]; by = bias[col + 1]; }
            if (row0 < M) {
                float rx = bx, ry = by;
                if (RESID) {
                    float2 hv = *reinterpret_cast<const float2*>(
                        Hres + (size_t)row0 * N + col);
                    rx += hv.x; ry += hv.y;
                }
                *reinterpret_cast<float2*>(C + (size_t)row0 * N + col) =
                    make_float2(acc[mf][nf][0] + rx, acc[mf][nf][1] + ry);
            }
            if (row0 + 8 < M) {
                float rx = bx, ry = by;
                if (RESID) {
                    float2 hv = *reinterpret_cast<const float2*>(
                        Hres + (size_t)(row0 + 8) * N + col);
                    rx += hv.x; ry += hv.y;
                }
                *reinterpret_cast<float2*>(C + (size_t)(row0 + 8) * N + col) =
                    make_float2(acc[mf][nf][2] + rx, acc[mf][nf][3] + ry);
            }
        }
    }
}

// ------------------------- launch --------------------------------------------
extern "C" void kernel_launch(void* const* d_in, const int* in_sizes, int n_in,
                              void* d_out, int out_size) {
    (void)in_sizes; (void)n_in; (void)out_size;
    const int*   x    = (const int*)  d_in[0];
    const int*   eidx = (const int*)  d_in[1];
    const int*   et   = (const int*)  d_in[2];
    const float* emb  = (const float*)d_in[3];
    const float* rel1 = (const float*)d_in[4];
    const float* Wn1  = (const float*)d_in[7];
    const float* bn1  = (const float*)d_in[8];
    const float* cw1  = (const float*)d_in[9];
    const float* gm1  = (const float*)d_in[10];
    const float* bt1  = (const float*)d_in[11];
    const float* rel2 = (const float*)d_in[12];
    const float* Wr2  = (const float*)d_in[13];
    const float* br2  = (const float*)d_in[14];
    const float* Wn2  = (const float*)d_in[15];
    const float* bn2  = (const float*)d_in[16];
    const float* cw2  = (const float*)d_in[17];
    const float* gm2  = (const float*)d_in[18];
    const float* bt2  = (const float*)d_in[19];

    float* out_h    = (float*)d_out;
    float* out_rels = out_h + (size_t)N_NODES * DIM;
    const int* src = eidx;
    const int* dst = eidx + N_EDGES;

    float *pH, *pHC, *pZ, *pTw, *pWt, *pWi, *pW;
    __half2 *pHH, *pHSH, *pRH, *pRSH;
    int *pDeg, *pOff, *pPos;
    int2* pEdges;
    cudaGetSymbolAddress((void**)&pH,    g_h);
    cudaGetSymbolAddress((void**)&pHC,   g_HC);
    cudaGetSymbolAddress((void**)&pZ,    g_Z);
    cudaGetSymbolAddress((void**)&pHH,   g_hH);
    cudaGetSymbolAddress((void**)&pHSH,  g_HSH);
    cudaGetSymbolAddress((void**)&pRH,   g_rH);
    cudaGetSymbolAddress((void**)&pRSH,  g_RSH);
    cudaGetSymbolAddress((void**)&pTw,   g_tw);
    cudaGetSymbolAddress((void**)&pWt,   g_wt);
    cudaGetSymbolAddress((void**)&pWi,   g_wi);
    cudaGetSymbolAddress((void**)&pW,    g_w);
    cudaGetSymbolAddress((void**)&pDeg,  g_deg);
    cudaGetSymbolAddress((void**)&pOff,  g_off);
    cudaGetSymbolAddress((void**)&pPos,  g_pos);
    cudaGetSymbolAddress((void**)&pEdges, g_edges);

    const float2* tw = (const float2*)pTw;
    const float2* wt = (const float2*)pWt;
    const float2* wi = (const float2*)pWi;
    __half2* pRH1  = pRH;
    __half2* pRH2  = pRH  + (size_t)NRELS * HROW2;
    __half2* pRSH1 = pRSH;
    __half2* pRSH2 = pRSH + (size_t)NRELS * SROW2;

    setup_kernel<<<(N_NODES + 255) / 256, 256>>>(pTw, pWt, pWi, cw1, cw2, pW, pDeg);
    hist_kernel<<<(N_EDGES + 255) / 256, 256>>>(dst, pDeg);
    scan_kernel<<<1, 1024>>>(pDeg, pOff, pPos);
    scatter_kernel<<<(N_EDGES + 255) / 256, 256>>>(src, dst, et, pPos, pEdges);

    // rel FFTs for both layers, hoisted out of the layer loop
    rel_fft_kernel<<<NRELS / 4, 256>>>(rel1, pRH1, pRSH1, tw, wt);
    rel_fft_kernel<<<NRELS / 4, 256>>>(rel2, pRH2, pRSH2, tw, wt);

    gather_fft_kernel<<<N_NODES / 4, 256>>>(x, emb, pH, pHH, pHSH, tw, wt);

    for (int L = 0; L < 2; L++) {
        const float* Wn = (L == 0) ? Wn1 : Wn2;
        const float* bn = (L == 0) ? bn1 : bn2;
        const float* gm = (L == 0) ? gm1 : gm2;
        const float* bt = (L == 0) ? bt1 : bt2;
        __half2* rH  = (L == 0) ? pRH1  : pRH2;
        __half2* RSH = (L == 0) ? pRSH1 : pRSH2;

        agg_inv_kernel<<<N_NODES / 4, 256>>>(pEdges, pOff, pHH, pHSH, rH, RSH,
                                             pW, 3 * L, pHC, tw, wi);
        bf16x3_gemm<true, true><<<dim3(2, (N_NODES + 127) / 128), 256>>>(
            pHC, Wn, pZ, bn, pH, N_NODES, DIM, DIM);
        if (L == 0) {
            epilogue_fft_kernel<true><<<N_NODES / 4, 256>>>(
                pZ, gm, bt, pH, pHH, pHSH, tw, wt);
        } else {
            epilogue_fft_kernel<false><<<N_NODES / 4, 256>>>(
                pZ, gm, bt, out_h, nullptr, nullptr, tw, wt);
        }
    }

    bf16x3_gemm<true, false><<<dim3(2, (NRELS + 127) / 128), 256>>>(
        rel2, Wr2, out_rels, br2, nullptr, NRELS, DIM, DIM);
}